// round 2
// baseline (speedup 1.0000x reference)
#include <cuda_runtime.h>
#include <cuda_bf16.h>
#include <math.h>

// Problem constants
#define Bd   4
#define Td   2048
#define Cd   1024
#define NHd  16
#define HSd  64
#define Md   (Bd * Td)          // 8192 rows
#define N_QKV (3 * Cd)          // 3072
#define KDIM Cd                 // 1024

// ---------------- scratch (device globals: allocation-free) ----------------
__device__ float g_Q[Bd * NHd * Td * HSd];   // 32 MB, [B,NH,T,HS]
__device__ float g_K[Bd * NHd * Td * HSd];
__device__ float g_V[Bd * NHd * Td * HSd];
__device__ float g_Y[Md * Cd];               // attention output, [B,T,C]

// ---------------- SGEMM 128x128 tile, BK=8, 256 thr, 8x8 microtile ----------

#define BM 128
#define BN 128
#define BK 8

// QKV GEMM: qkv = x @ W_attn + b_attn, scattered to Q/K/V [B,NH,T,HS]
__global__ __launch_bounds__(256)
void gemm_qkv_kernel(const float* __restrict__ A,      // x  [M, K]
                     const float* __restrict__ Bm,     // W_attn [K, 3C]
                     const float* __restrict__ bias)   // [3C]
{
    __shared__ float As[BK][BM];
    __shared__ float Bs[BK][BN];

    const int tid = threadIdx.x;
    const int tx = tid & 15;          // 0..15  (col group)
    const int ty = tid >> 4;          // 0..15  (row group)
    const int rowBase = blockIdx.y * BM;
    const int colBase = blockIdx.x * BN;

    const int aRow = tid >> 1;        // 0..127
    const int aCol = (tid & 1) << 2;  // 0 or 4
    const int bRow = tid >> 5;        // 0..7
    const int bCol = (tid & 31) << 2; // 0..124

    float acc[8][8];
#pragma unroll
    for (int i = 0; i < 8; i++)
#pragma unroll
        for (int j = 0; j < 8; j++) acc[i][j] = 0.f;

    for (int k0 = 0; k0 < KDIM; k0 += BK) {
        float4 av = *(const float4*)&A[(rowBase + aRow) * KDIM + k0 + aCol];
        As[aCol + 0][aRow] = av.x;
        As[aCol + 1][aRow] = av.y;
        As[aCol + 2][aRow] = av.z;
        As[aCol + 3][aRow] = av.w;
        *(float4*)&Bs[bRow][bCol] =
            *(const float4*)&Bm[(k0 + bRow) * N_QKV + colBase + bCol];
        __syncthreads();

#pragma unroll
        for (int k = 0; k < BK; k++) {
            float a[8], b[8];
#pragma unroll
            for (int i = 0; i < 4; i++) {
                ((float4*)a)[0] = *(const float4*)&As[k][ty * 8];
                ((float4*)a)[1] = *(const float4*)&As[k][ty * 8 + 4];
                ((float4*)b)[0] = *(const float4*)&Bs[k][tx * 8];
                ((float4*)b)[1] = *(const float4*)&Bs[k][tx * 8 + 4];
                break;
            }
#pragma unroll
            for (int i = 0; i < 8; i++)
#pragma unroll
                for (int j = 0; j < 8; j++) acc[i][j] += a[i] * b[j];
        }
        __syncthreads();
    }

    // epilogue: bias + scatter into Q/K/V [B,NH,T,HS]
#pragma unroll
    for (int i = 0; i < 8; i++) {
        const int r = rowBase + ty * 8 + i;
        const int bb = r / Td;
        const int t  = r % Td;
#pragma unroll
        for (int j = 0; j < 8; j++) {
            const int c = colBase + tx * 8 + j;
            const float val = acc[i][j] + bias[c];
            const int which = c / Cd;        // 0=q, 1=k, 2=v
            const int inner = c % Cd;
            const int h = inner / HSd;
            const int d = inner % HSd;
            float* dst = (which == 0) ? g_Q : (which == 1) ? g_K : g_V;
            dst[((bb * NHd + h) * Td + t) * HSd + d] = val;
        }
    }
}

// Proj GEMM: out = Y @ W_proj + b_proj
__global__ __launch_bounds__(256)
void gemm_proj_kernel(const float* __restrict__ Bm,    // W_proj [K, C]
                      const float* __restrict__ bias,  // [C]
                      float* __restrict__ out)         // [M, C]
{
    __shared__ float As[BK][BM];
    __shared__ float Bs[BK][BN];

    const int tid = threadIdx.x;
    const int tx = tid & 15;
    const int ty = tid >> 4;
    const int rowBase = blockIdx.y * BM;
    const int colBase = blockIdx.x * BN;

    const int aRow = tid >> 1;
    const int aCol = (tid & 1) << 2;
    const int bRow = tid >> 5;
    const int bCol = (tid & 31) << 2;

    float acc[8][8];
#pragma unroll
    for (int i = 0; i < 8; i++)
#pragma unroll
        for (int j = 0; j < 8; j++) acc[i][j] = 0.f;

    for (int k0 = 0; k0 < KDIM; k0 += BK) {
        float4 av = *(const float4*)&g_Y[(rowBase + aRow) * KDIM + k0 + aCol];
        As[aCol + 0][aRow] = av.x;
        As[aCol + 1][aRow] = av.y;
        As[aCol + 2][aRow] = av.z;
        As[aCol + 3][aRow] = av.w;
        *(float4*)&Bs[bRow][bCol] =
            *(const float4*)&Bm[(k0 + bRow) * Cd + colBase + bCol];
        __syncthreads();

#pragma unroll
        for (int k = 0; k < BK; k++) {
            float a[8], b[8];
            ((float4*)a)[0] = *(const float4*)&As[k][ty * 8];
            ((float4*)a)[1] = *(const float4*)&As[k][ty * 8 + 4];
            ((float4*)b)[0] = *(const float4*)&Bs[k][tx * 8];
            ((float4*)b)[1] = *(const float4*)&Bs[k][tx * 8 + 4];
#pragma unroll
            for (int i = 0; i < 8; i++)
#pragma unroll
                for (int j = 0; j < 8; j++) acc[i][j] += a[i] * b[j];
        }
        __syncthreads();
    }

#pragma unroll
    for (int i = 0; i < 8; i++) {
        const int r = rowBase + ty * 8 + i;
#pragma unroll
        for (int j = 0; j < 8; j += 4) {
            const int c = colBase + tx * 8 + j;
            float4 v;
            v.x = acc[i][j + 0] + bias[c + 0];
            v.y = acc[i][j + 1] + bias[c + 1];
            v.z = acc[i][j + 2] + bias[c + 2];
            v.w = acc[i][j + 3] + bias[c + 3];
            *(float4*)&out[r * Cd + c] = v;
        }
    }
}

// ---------------- flash attention (fp32, 1 thread = 1 query row) ------------
// grid (T/128, NH, B), 128 threads. K/V staged in SMEM 64-row tiles.
__global__ __launch_bounds__(128)
void attn_kernel()
{
    const int b = blockIdx.z;
    const int h = blockIdx.y;
    const int qi = blockIdx.x * 128 + threadIdx.x;
    const float scale = 0.125f;   // 1/sqrt(64)

    __shared__ float Ks[64][64];
    __shared__ float Vs[64][64];

    const float* Kbase = &g_K[((size_t)(b * NHd + h) * Td) * HSd];
    const float* Vbase = &g_V[((size_t)(b * NHd + h) * Td) * HSd];
    const float* qptr  = &g_Q[(((size_t)(b * NHd + h) * Td) + qi) * HSd];

    float q[HSd];
#pragma unroll
    for (int d = 0; d < HSd; d += 4) {
        float4 v4 = *(const float4*)&qptr[d];
        q[d + 0] = v4.x * scale;
        q[d + 1] = v4.y * scale;
        q[d + 2] = v4.z * scale;
        q[d + 3] = v4.w * scale;
    }

    float m = -1e30f, l = 0.f;
    float acc[HSd];
#pragma unroll
    for (int d = 0; d < HSd; d++) acc[d] = 0.f;

    const int ntiles = blockIdx.x * 2 + 2;   // causal: tiles up to q block end
    for (int tile = 0; tile < ntiles; tile++) {
        const int base = tile * 64 * HSd;
#pragma unroll
        for (int i = 0; i < 8; i++) {
            const int f = threadIdx.x + i * 128;  // float4 index 0..1023
            const int r = f >> 4;
            const int c4 = (f & 15) << 2;
            *(float4*)&Ks[r][c4] = *(const float4*)&Kbase[base + r * HSd + c4];
            *(float4*)&Vs[r][c4] = *(const float4*)&Vbase[base + r * HSd + c4];
        }
        __syncthreads();

        const int jmax = min(64, qi - tile * 64 + 1);
        for (int j = 0; j < jmax; j++) {
            float s = 0.f;
#pragma unroll
            for (int d = 0; d < HSd; d++) s += q[d] * Ks[j][d];

            if (s > m) {
                const float corr = __expf(m - s);
                m = s;
                l = l * corr + 1.0f;
#pragma unroll
                for (int d = 0; d < HSd; d++)
                    acc[d] = acc[d] * corr + Vs[j][d];
            } else {
                const float p = __expf(s - m);
                l += p;
#pragma unroll
                for (int d = 0; d < HSd; d++)
                    acc[d] += p * Vs[j][d];
            }
        }
        __syncthreads();
    }

    const float inv = 1.0f / l;
    float* yptr = &g_Y[((size_t)(b * Td + qi)) * Cd + h * HSd];
#pragma unroll
    for (int d = 0; d < HSd; d += 4) {
        float4 v;
        v.x = acc[d + 0] * inv;
        v.y = acc[d + 1] * inv;
        v.z = acc[d + 2] * inv;
        v.w = acc[d + 3] * inv;
        *(float4*)&yptr[d] = v;
    }
}

// ---------------- launch ----------------------------------------------------
extern "C" void kernel_launch(void* const* d_in, const int* in_sizes, int n_in,
                              void* d_out, int out_size)
{
    const float* x      = (const float*)d_in[0];
    const float* W_attn = (const float*)d_in[1];
    const float* b_attn = (const float*)d_in[2];
    const float* W_proj = (const float*)d_in[3];
    const float* b_proj = (const float*)d_in[4];
    float* out = (float*)d_out;

    (void)in_sizes; (void)n_in; (void)out_size;

    dim3 gQKV(N_QKV / BN, Md / BM);       // (24, 64)
    gemm_qkv_kernel<<<gQKV, 256>>>(x, W_attn, b_attn);

    dim3 gAtt(Td / 128, NHd, Bd);         // (16, 16, 4)
    attn_kernel<<<gAtt, 128>>>();

    dim3 gProj(Cd / BN, Md / BM);         // (8, 64)
    gemm_proj_kernel<<<gProj, 256>>>(W_proj, b_proj, out);
}

// round 4
// speedup vs baseline: 1.3123x; 1.3123x over previous
#include <cuda_runtime.h>
#include <cuda_bf16.h>
#include <math.h>
#include <stdint.h>

// Problem constants
#define Bd   4
#define Td   2048
#define Cd   1024
#define NHd  16
#define HSd  64
#define Md   (Bd * Td)          // 8192 rows
#define N_QKV (3 * Cd)          // 3072
#define KDIM Cd                 // 1024

// ---------------- scratch (device globals: allocation-free) ----------------
__device__ float g_Q[Bd * NHd * Td * HSd];   // 32 MB, [B,NH,T,HS]
__device__ float g_K[Bd * NHd * Td * HSd];
__device__ float g_V[Bd * NHd * Td * HSd];
__device__ float g_Y[Md * Cd];               // attention output, [B,T,C]

// ---------------- TF32 tensor-core GEMM -------------------------------------
// 128x128 tile, BK=16, 256 thr = 8 warps, warp tile 32x64 (2x8 mma m16n8k8)

#define BM 128
#define BN 128
#define BK 16
#define SPAD 132   // BM+4 / BN+4 padded stride (uints)

__device__ __forceinline__ uint32_t f2tf32(float f) {
    uint32_t r;
    asm("cvt.rna.tf32.f32 %0, %1;" : "=r"(r) : "f"(f));
    return r;
}

__device__ __forceinline__ void mma_tf32(float c[4], const uint32_t a[4],
                                         const uint32_t b[2]) {
    asm volatile(
        "mma.sync.aligned.m16n8k8.row.col.f32.tf32.tf32.f32 "
        "{%0,%1,%2,%3}, {%4,%5,%6,%7}, {%8,%9}, {%0,%1,%2,%3};"
        : "+f"(c[0]), "+f"(c[1]), "+f"(c[2]), "+f"(c[3])
        : "r"(a[0]), "r"(a[1]), "r"(a[2]), "r"(a[3]), "r"(b[0]), "r"(b[1]));
}

// QKV == true: scatter epilogue into g_Q/g_K/g_V (out unused)
// QKV == false: out = acc + bias, [M, NDIM]
// A_FROM_GY == true: ignore A argument, read g_Y (device-side symbol
// resolution; passing a __device__ global's address from host code yields the
// host shadow address, which GB300's ATS silently dereferences -> garbage).
template <int NDIM, bool QKV, bool A_FROM_GY>
__global__ __launch_bounds__(256)
void gemm_tf32_kernel(const float* __restrict__ A,     // [M, KDIM]
                      const float* __restrict__ Bm,    // [KDIM, NDIM]
                      const float* __restrict__ bias,  // [NDIM]
                      float* __restrict__ out)
{
    __shared__ uint32_t As[BK][SPAD];   // k-major: As[k][m]
    __shared__ uint32_t Bs[BK][SPAD];   // k-major: Bs[k][n]

    const float* Aeff = A_FROM_GY ? (const float*)g_Y : A;

    const int tid = threadIdx.x;
    const int lane = tid & 31;
    const int wid = tid >> 5;
    const int warpM = wid & 3;          // 4 warps along M, 32 rows each
    const int warpN = wid >> 2;         // 2 warps along N, 64 cols each
    const int g   = lane >> 2;          // groupID 0..7
    const int tig = lane & 3;           // threadInGroup 0..3

    const int rowBase = blockIdx.y * BM;
    const int colBase = blockIdx.x * BN;

    const int aRow = tid >> 1;          // 0..127
    const int aCol = (tid & 1) << 3;    // 0 or 8
    const int bRow = tid >> 4;          // 0..15
    const int bCol = (tid & 15) << 3;   // 0..120

    float acc[2][8][4];
#pragma unroll
    for (int mt = 0; mt < 2; mt++)
#pragma unroll
        for (int nt = 0; nt < 8; nt++)
#pragma unroll
            for (int i = 0; i < 4; i++) acc[mt][nt][i] = 0.f;

    const float* Aptr = &Aeff[(rowBase + aRow) * KDIM + aCol];
    const float* Bptr = &Bm[bRow * NDIM + colBase + bCol];

    for (int k0 = 0; k0 < KDIM; k0 += BK) {
        // --- stage A (transpose to k-major) + convert to tf32 ---
        float4 av0 = *(const float4*)&Aptr[k0];
        float4 av1 = *(const float4*)&Aptr[k0 + 4];
        As[aCol + 0][aRow] = f2tf32(av0.x);
        As[aCol + 1][aRow] = f2tf32(av0.y);
        As[aCol + 2][aRow] = f2tf32(av0.z);
        As[aCol + 3][aRow] = f2tf32(av0.w);
        As[aCol + 4][aRow] = f2tf32(av1.x);
        As[aCol + 5][aRow] = f2tf32(av1.y);
        As[aCol + 6][aRow] = f2tf32(av1.z);
        As[aCol + 7][aRow] = f2tf32(av1.w);

        // --- stage B + convert to tf32 ---
        float4 bv0 = *(const float4*)&Bptr[k0 * NDIM];
        float4 bv1 = *(const float4*)&Bptr[k0 * NDIM + 4];
        uint4 w0, w1;
        w0.x = f2tf32(bv0.x); w0.y = f2tf32(bv0.y);
        w0.z = f2tf32(bv0.z); w0.w = f2tf32(bv0.w);
        w1.x = f2tf32(bv1.x); w1.y = f2tf32(bv1.y);
        w1.z = f2tf32(bv1.z); w1.w = f2tf32(bv1.w);
        *(uint4*)&Bs[bRow][bCol]     = w0;
        *(uint4*)&Bs[bRow][bCol + 4] = w1;
        __syncthreads();

        // --- compute: two k-steps of 8 ---
#pragma unroll
        for (int ks = 0; ks < BK; ks += 8) {
            uint32_t af[2][4];
            uint32_t bf[8][2];
#pragma unroll
            for (int mt = 0; mt < 2; mt++) {
                const int m0 = warpM * 32 + mt * 16 + g;
                af[mt][0] = As[ks + tig][m0];
                af[mt][1] = As[ks + tig][m0 + 8];
                af[mt][2] = As[ks + tig + 4][m0];
                af[mt][3] = As[ks + tig + 4][m0 + 8];
            }
#pragma unroll
            for (int nt = 0; nt < 8; nt++) {
                const int n0 = warpN * 64 + nt * 8 + g;
                bf[nt][0] = Bs[ks + tig][n0];
                bf[nt][1] = Bs[ks + tig + 4][n0];
            }
#pragma unroll
            for (int mt = 0; mt < 2; mt++)
#pragma unroll
                for (int nt = 0; nt < 8; nt++)
                    mma_tf32(acc[mt][nt], af[mt], bf[nt]);
        }
        __syncthreads();
    }

    // ---------------- epilogue ----------------
#pragma unroll
    for (int mt = 0; mt < 2; mt++) {
        const int r0 = rowBase + warpM * 32 + mt * 16 + g;
        const int r1 = r0 + 8;
#pragma unroll
        for (int nt = 0; nt < 8; nt++) {
            const int c = colBase + warpN * 64 + nt * 8 + 2 * tig;
            const float b0 = bias[c];
            const float b1 = bias[c + 1];
            if (QKV) {
                // scatter into [B,NH,T,HS]
#pragma unroll
                for (int e = 0; e < 4; e++) {
                    const int r  = (e < 2) ? r0 : r1;
                    const int cc = c + (e & 1);
                    const float val = acc[mt][nt][e] + ((e & 1) ? b1 : b0);
                    const int bb = r / Td;
                    const int t  = r % Td;
                    const int which = cc / Cd;
                    const int inner = cc % Cd;
                    const int h = inner / HSd;
                    const int d = inner % HSd;
                    float* dst = (which == 0) ? g_Q : (which == 1) ? g_K : g_V;
                    dst[((bb * NHd + h) * Td + t) * HSd + d] = val;
                }
            } else {
                float2 v0, v1;
                v0.x = acc[mt][nt][0] + b0;
                v0.y = acc[mt][nt][1] + b1;
                v1.x = acc[mt][nt][2] + b0;
                v1.y = acc[mt][nt][3] + b1;
                *(float2*)&out[r0 * NDIM + c] = v0;
                *(float2*)&out[r1 * NDIM + c] = v1;
            }
        }
    }
}

// ---------------- flash attention (fp32, 1 thread = 1 query row) ------------
__global__ __launch_bounds__(128)
void attn_kernel()
{
    const int b = blockIdx.z;
    const int h = blockIdx.y;
    const int qi = blockIdx.x * 128 + threadIdx.x;
    const float scale = 0.125f;   // 1/sqrt(64)

    __shared__ float Ks[64][64];
    __shared__ float Vs[64][64];

    const float* Kbase = &g_K[((size_t)(b * NHd + h) * Td) * HSd];
    const float* Vbase = &g_V[((size_t)(b * NHd + h) * Td) * HSd];
    const float* qptr  = &g_Q[(((size_t)(b * NHd + h) * Td) + qi) * HSd];

    float q[HSd];
#pragma unroll
    for (int d = 0; d < HSd; d += 4) {
        float4 v4 = *(const float4*)&qptr[d];
        q[d + 0] = v4.x * scale;
        q[d + 1] = v4.y * scale;
        q[d + 2] = v4.z * scale;
        q[d + 3] = v4.w * scale;
    }

    float m = -1e30f, l = 0.f;
    float acc[HSd];
#pragma unroll
    for (int d = 0; d < HSd; d++) acc[d] = 0.f;

    const int ntiles = blockIdx.x * 2 + 2;
    for (int tile = 0; tile < ntiles; tile++) {
        const int base = tile * 64 * HSd;
#pragma unroll
        for (int i = 0; i < 8; i++) {
            const int f = threadIdx.x + i * 128;
            const int r = f >> 4;
            const int c4 = (f & 15) << 2;
            *(float4*)&Ks[r][c4] = *(const float4*)&Kbase[base + r * HSd + c4];
            *(float4*)&Vs[r][c4] = *(const float4*)&Vbase[base + r * HSd + c4];
        }
        __syncthreads();

        const int jmax = min(64, qi - tile * 64 + 1);
        for (int j = 0; j < jmax; j++) {
            float s = 0.f;
#pragma unroll
            for (int d = 0; d < HSd; d++) s += q[d] * Ks[j][d];

            if (s > m) {
                const float corr = __expf(m - s);
                m = s;
                l = l * corr + 1.0f;
#pragma unroll
                for (int d = 0; d < HSd; d++)
                    acc[d] = acc[d] * corr + Vs[j][d];
            } else {
                const float p = __expf(s - m);
                l += p;
#pragma unroll
                for (int d = 0; d < HSd; d++)
                    acc[d] += p * Vs[j][d];
            }
        }
        __syncthreads();
    }

    const float inv = 1.0f / l;
    float* yptr = &g_Y[((size_t)(b * Td + qi)) * Cd + h * HSd];
#pragma unroll
    for (int d = 0; d < HSd; d += 4) {
        float4 v;
        v.x = acc[d + 0] * inv;
        v.y = acc[d + 1] * inv;
        v.z = acc[d + 2] * inv;
        v.w = acc[d + 3] * inv;
        *(float4*)&yptr[d] = v;
    }
}

// ---------------- launch ----------------------------------------------------
extern "C" void kernel_launch(void* const* d_in, const int* in_sizes, int n_in,
                              void* d_out, int out_size)
{
    const float* x      = (const float*)d_in[0];
    const float* W_attn = (const float*)d_in[1];
    const float* b_attn = (const float*)d_in[2];
    const float* W_proj = (const float*)d_in[3];
    const float* b_proj = (const float*)d_in[4];
    float* out = (float*)d_out;

    (void)in_sizes; (void)n_in; (void)out_size;

    dim3 gQKV(N_QKV / BN, Md / BM);       // (24, 64)
    gemm_tf32_kernel<N_QKV, true, false><<<gQKV, 256>>>(x, W_attn, b_attn, nullptr);

    dim3 gAtt(Td / 128, NHd, Bd);         // (16, 16, 4)
    attn_kernel<<<gAtt, 128>>>();

    dim3 gProj(Cd / BN, Md / BM);         // (8, 64)
    gemm_tf32_kernel<Cd, false, true><<<gProj, 256>>>(nullptr, W_proj, b_proj, out);
}

// round 5
// speedup vs baseline: 1.8400x; 1.4022x over previous
#include <cuda_runtime.h>
#include <cuda_bf16.h>
#include <math.h>
#include <stdint.h>

// Problem constants
#define Bd   4
#define Td   2048
#define Cd   1024
#define NHd  16
#define HSd  64
#define Md   (Bd * Td)          // 8192 rows
#define N_QKV (3 * Cd)          // 3072
#define KDIM Cd                 // 1024

// ---------------- scratch (device globals: allocation-free) ----------------
__device__ float g_Q[Bd * NHd * Td * HSd];   // 32 MB, [B,NH,T,HS]
__device__ float g_K[Bd * NHd * Td * HSd];
__device__ float g_V[Bd * NHd * Td * HSd];
__device__ float g_Y[Md * Cd];               // attention output, [B,T,C]

// ---------------- TF32 helpers ----------------------------------------------
__device__ __forceinline__ uint32_t f2tf32(float f) {
    uint32_t r;
    asm("cvt.rna.tf32.f32 %0, %1;" : "=r"(r) : "f"(f));
    return r;
}

__device__ __forceinline__ void mma_tf32(float c[4], const uint32_t a[4],
                                         const uint32_t b[2]) {
    asm volatile(
        "mma.sync.aligned.m16n8k8.row.col.f32.tf32.tf32.f32 "
        "{%0,%1,%2,%3}, {%4,%5,%6,%7}, {%8,%9}, {%0,%1,%2,%3};"
        : "+f"(c[0]), "+f"(c[1]), "+f"(c[2]), "+f"(c[3])
        : "r"(a[0]), "r"(a[1]), "r"(a[2]), "r"(a[3]), "r"(b[0]), "r"(b[1]));
}

// ---------------- TF32 tensor-core GEMM (unchanged from R3, passing) --------
#define BM 128
#define BN 128
#define BK 16
#define SPAD 132

template <int NDIM, bool QKV, bool A_FROM_GY>
__global__ __launch_bounds__(256)
void gemm_tf32_kernel(const float* __restrict__ A,
                      const float* __restrict__ Bm,
                      const float* __restrict__ bias,
                      float* __restrict__ out)
{
    __shared__ uint32_t As[BK][SPAD];
    __shared__ uint32_t Bs[BK][SPAD];

    const float* Aeff = A_FROM_GY ? (const float*)g_Y : A;

    const int tid = threadIdx.x;
    const int lane = tid & 31;
    const int wid = tid >> 5;
    const int warpM = wid & 3;
    const int warpN = wid >> 2;
    const int g   = lane >> 2;
    const int tig = lane & 3;

    const int rowBase = blockIdx.y * BM;
    const int colBase = blockIdx.x * BN;

    const int aRow = tid >> 1;
    const int aCol = (tid & 1) << 3;
    const int bRow = tid >> 4;
    const int bCol = (tid & 15) << 3;

    float acc[2][8][4];
#pragma unroll
    for (int mt = 0; mt < 2; mt++)
#pragma unroll
        for (int nt = 0; nt < 8; nt++)
#pragma unroll
            for (int i = 0; i < 4; i++) acc[mt][nt][i] = 0.f;

    const float* Aptr = &Aeff[(rowBase + aRow) * KDIM + aCol];
    const float* Bptr = &Bm[bRow * NDIM + colBase + bCol];

    for (int k0 = 0; k0 < KDIM; k0 += BK) {
        float4 av0 = *(const float4*)&Aptr[k0];
        float4 av1 = *(const float4*)&Aptr[k0 + 4];
        As[aCol + 0][aRow] = f2tf32(av0.x);
        As[aCol + 1][aRow] = f2tf32(av0.y);
        As[aCol + 2][aRow] = f2tf32(av0.z);
        As[aCol + 3][aRow] = f2tf32(av0.w);
        As[aCol + 4][aRow] = f2tf32(av1.x);
        As[aCol + 5][aRow] = f2tf32(av1.y);
        As[aCol + 6][aRow] = f2tf32(av1.z);
        As[aCol + 7][aRow] = f2tf32(av1.w);

        float4 bv0 = *(const float4*)&Bptr[k0 * NDIM];
        float4 bv1 = *(const float4*)&Bptr[k0 * NDIM + 4];
        uint4 w0, w1;
        w0.x = f2tf32(bv0.x); w0.y = f2tf32(bv0.y);
        w0.z = f2tf32(bv0.z); w0.w = f2tf32(bv0.w);
        w1.x = f2tf32(bv1.x); w1.y = f2tf32(bv1.y);
        w1.z = f2tf32(bv1.z); w1.w = f2tf32(bv1.w);
        *(uint4*)&Bs[bRow][bCol]     = w0;
        *(uint4*)&Bs[bRow][bCol + 4] = w1;
        __syncthreads();

#pragma unroll
        for (int ks = 0; ks < BK; ks += 8) {
            uint32_t af[2][4];
            uint32_t bf[8][2];
#pragma unroll
            for (int mt = 0; mt < 2; mt++) {
                const int m0 = warpM * 32 + mt * 16 + g;
                af[mt][0] = As[ks + tig][m0];
                af[mt][1] = As[ks + tig][m0 + 8];
                af[mt][2] = As[ks + tig + 4][m0];
                af[mt][3] = As[ks + tig + 4][m0 + 8];
            }
#pragma unroll
            for (int nt = 0; nt < 8; nt++) {
                const int n0 = warpN * 64 + nt * 8 + g;
                bf[nt][0] = Bs[ks + tig][n0];
                bf[nt][1] = Bs[ks + tig + 4][n0];
            }
#pragma unroll
            for (int mt = 0; mt < 2; mt++)
#pragma unroll
                for (int nt = 0; nt < 8; nt++)
                    mma_tf32(acc[mt][nt], af[mt], bf[nt]);
        }
        __syncthreads();
    }

#pragma unroll
    for (int mt = 0; mt < 2; mt++) {
        const int r0 = rowBase + warpM * 32 + mt * 16 + g;
        const int r1 = r0 + 8;
#pragma unroll
        for (int nt = 0; nt < 8; nt++) {
            const int c = colBase + warpN * 64 + nt * 8 + 2 * tig;
            const float b0 = bias[c];
            const float b1 = bias[c + 1];
            if (QKV) {
#pragma unroll
                for (int e = 0; e < 4; e++) {
                    const int r  = (e < 2) ? r0 : r1;
                    const int cc = c + (e & 1);
                    const float val = acc[mt][nt][e] + ((e & 1) ? b1 : b0);
                    const int bb = r / Td;
                    const int t  = r % Td;
                    const int which = cc / Cd;
                    const int inner = cc % Cd;
                    const int h = inner / HSd;
                    const int d = inner % HSd;
                    float* dst = (which == 0) ? g_Q : (which == 1) ? g_K : g_V;
                    dst[((bb * NHd + h) * Td + t) * HSd + d] = val;
                }
            } else {
                float2 v0, v1;
                v0.x = acc[mt][nt][0] + b0;
                v0.y = acc[mt][nt][1] + b1;
                v1.x = acc[mt][nt][2] + b0;
                v1.y = acc[mt][nt][3] + b1;
                *(float2*)&out[r0 * NDIM + c] = v0;
                *(float2*)&out[r1 * NDIM + c] = v1;
            }
        }
    }
}

// ---------------- tensor-core flash attention --------------------------------
// 1 CTA = 128 query rows of one (b,h). 8 warps x 16 rows. Bc=64 key tiles.
// Same m16n8k8 tf32 fragment mappings as the (passing) GEMM:
//   A: a0=(g,tig) a1=(g+8,tig) a2=(g,tig+4) a3=(g+8,tig+4)
//   B: b0=(k=tig,n=g) b1=(k=tig+4,n=g)
//   C: c0=(g,2tig) c1=(g,2tig+1) c2=(g+8,2tig) c3=(g+8,2tig+1)

#define KS_STRIDE 68   // conflict-free for g-indexed row reads
#define VS_STRIDE 72   // conflict-free for tig-indexed row reads
#define PS_STRIDE 68
#define SMEM_KS_U   (64 * KS_STRIDE)                 // 4352 uints
#define SMEM_VS_U   (64 * VS_STRIDE)                 // 4608
#define SMEM_PS_U   (8 * 16 * PS_STRIDE)             // 8704 (aliases Q staging)
#define ATTN_SMEM_BYTES ((SMEM_KS_U + SMEM_VS_U + SMEM_PS_U) * 4)  // 70656

__global__ __launch_bounds__(256)
void attn_mma_kernel()
{
    extern __shared__ uint32_t smem[];
    uint32_t* Ks = smem;
    uint32_t* Vs = smem + SMEM_KS_U;
    uint32_t* Ps = smem + SMEM_KS_U + SMEM_VS_U;   // also Q staging (aliased)
    uint32_t* Qs = Ps;

    const int b = blockIdx.z;
    const int h = blockIdx.y;
    const int qbase = blockIdx.x * 128;

    const int tid  = threadIdx.x;
    const int lane = tid & 31;
    const int w    = tid >> 5;          // warp 0..7
    const int g    = lane >> 2;         // 0..7
    const int tig  = lane & 3;          // 0..3

    const size_t headOff = (size_t)(b * NHd + h) * Td * HSd;
    const float* Kg = &g_K[headOff];
    const float* Vg = &g_V[headOff];
    const float* Qg = &g_Q[headOff + (size_t)qbase * HSd];

    // ---- stage Q (scaled, tf32) into Qs [128][68] ----
#pragma unroll
    for (int j = 0; j < 8; j++) {
        const int f = tid + j * 256;        // float4 idx 0..2047
        const int r = f >> 4;
        const int c4 = (f & 15) << 2;
        float4 v = *(const float4*)&Qg[r * HSd + c4];
        uint4 u;
        u.x = f2tf32(v.x * 0.125f);
        u.y = f2tf32(v.y * 0.125f);
        u.z = f2tf32(v.z * 0.125f);
        u.w = f2tf32(v.w * 0.125f);
        *(uint4*)&Qs[r * PS_STRIDE + c4] = u;
    }
    __syncthreads();

    // ---- preload Q fragments (16 rows x 64 d per warp) ----
    const int qr0 = w * 16 + g;
    const int qr1 = qr0 + 8;
    uint32_t qf[8][4];
#pragma unroll
    for (int kc = 0; kc < 8; kc++) {
        qf[kc][0] = Qs[qr0 * PS_STRIDE + kc * 8 + tig];
        qf[kc][1] = Qs[qr1 * PS_STRIDE + kc * 8 + tig];
        qf[kc][2] = Qs[qr0 * PS_STRIDE + kc * 8 + tig + 4];
        qf[kc][3] = Qs[qr1 * PS_STRIDE + kc * 8 + tig + 4];
    }

    const int qrow0 = qbase + qr0;       // global query rows
    const int qrow1 = qbase + qr1;

    float oacc[8][4];
#pragma unroll
    for (int nt = 0; nt < 8; nt++)
#pragma unroll
        for (int e = 0; e < 4; e++) oacc[nt][e] = 0.f;
    float m0 = -1e30f, m1 = -1e30f, l0 = 0.f, l1 = 0.f;

    uint32_t* Psw = Ps + w * 16 * PS_STRIDE;
    const int ntiles = 2 * blockIdx.x + 2;

    for (int t = 0; t < ntiles; t++) {
        __syncthreads();   // protect Ks/Vs (and first-iter: Qs reads done)

        // ---- load K,V tile (64x64) as tf32 ----
        const float* Kt = Kg + t * 64 * HSd;
        const float* Vt = Vg + t * 64 * HSd;
#pragma unroll
        for (int j = 0; j < 4; j++) {
            const int f = tid + j * 256;     // float4 idx 0..1023
            const int r = f >> 4;
            const int c4 = (f & 15) << 2;
            float4 kv = *(const float4*)&Kt[r * HSd + c4];
            uint4 ku;
            ku.x = f2tf32(kv.x); ku.y = f2tf32(kv.y);
            ku.z = f2tf32(kv.z); ku.w = f2tf32(kv.w);
            *(uint4*)&Ks[r * KS_STRIDE + c4] = ku;
            float4 vv = *(const float4*)&Vt[r * HSd + c4];
            uint4 vu;
            vu.x = f2tf32(vv.x); vu.y = f2tf32(vv.y);
            vu.z = f2tf32(vv.z); vu.w = f2tf32(vv.w);
            *(uint4*)&Vs[r * VS_STRIDE + c4] = vu;
        }
        __syncthreads();

        // ---- S = Q K^T (16 x 64 per warp) ----
        float sacc[8][4];
#pragma unroll
        for (int nt = 0; nt < 8; nt++)
#pragma unroll
            for (int e = 0; e < 4; e++) sacc[nt][e] = 0.f;

#pragma unroll
        for (int kc = 0; kc < 8; kc++) {
            uint32_t bf[8][2];
#pragma unroll
            for (int nt = 0; nt < 8; nt++) {
                bf[nt][0] = Ks[(nt * 8 + g) * KS_STRIDE + kc * 8 + tig];
                bf[nt][1] = Ks[(nt * 8 + g) * KS_STRIDE + kc * 8 + tig + 4];
            }
#pragma unroll
            for (int nt = 0; nt < 8; nt++)
                mma_tf32(sacc[nt], qf[kc], bf[nt]);
        }

        // ---- causal mask (only the last two tiles can cross the diagonal) --
        if (t >= 2 * (int)blockIdx.x) {
            const int colb = t * 64;
#pragma unroll
            for (int nt = 0; nt < 8; nt++) {
                const int c0 = colb + nt * 8 + 2 * tig;
                if (c0     > qrow0) sacc[nt][0] = -1e30f;
                if (c0 + 1 > qrow0) sacc[nt][1] = -1e30f;
                if (c0     > qrow1) sacc[nt][2] = -1e30f;
                if (c0 + 1 > qrow1) sacc[nt][3] = -1e30f;
            }
        }

        // ---- online softmax ----
        float mx0 = -1e30f, mx1 = -1e30f;
#pragma unroll
        for (int nt = 0; nt < 8; nt++) {
            mx0 = fmaxf(mx0, fmaxf(sacc[nt][0], sacc[nt][1]));
            mx1 = fmaxf(mx1, fmaxf(sacc[nt][2], sacc[nt][3]));
        }
        mx0 = fmaxf(mx0, __shfl_xor_sync(0xffffffffu, mx0, 1));
        mx0 = fmaxf(mx0, __shfl_xor_sync(0xffffffffu, mx0, 2));
        mx1 = fmaxf(mx1, __shfl_xor_sync(0xffffffffu, mx1, 1));
        mx1 = fmaxf(mx1, __shfl_xor_sync(0xffffffffu, mx1, 2));

        const float nm0 = fmaxf(m0, mx0);
        const float nm1 = fmaxf(m1, mx1);
        const float corr0 = __expf(m0 - nm0);
        const float corr1 = __expf(m1 - nm1);
        m0 = nm0; m1 = nm1;

        float sum0 = 0.f, sum1 = 0.f;
#pragma unroll
        for (int nt = 0; nt < 8; nt++) {
            const float p0 = __expf(sacc[nt][0] - nm0);
            const float p1 = __expf(sacc[nt][1] - nm0);
            const float p2 = __expf(sacc[nt][2] - nm1);
            const float p3 = __expf(sacc[nt][3] - nm1);
            sum0 += p0 + p1;
            sum1 += p2 + p3;
            uint2 u0; u0.x = f2tf32(p0); u0.y = f2tf32(p1);
            uint2 u1; u1.x = f2tf32(p2); u1.y = f2tf32(p3);
            *(uint2*)&Psw[g * PS_STRIDE + nt * 8 + 2 * tig] = u0;
            *(uint2*)&Psw[(g + 8) * PS_STRIDE + nt * 8 + 2 * tig] = u1;
            oacc[nt][0] *= corr0; oacc[nt][1] *= corr0;
            oacc[nt][2] *= corr1; oacc[nt][3] *= corr1;
        }
        l0 = l0 * corr0 + sum0;
        l1 = l1 * corr1 + sum1;
        __syncwarp();

        // ---- O += P V (16 x 64 per warp, K=64 keys) ----
#pragma unroll
        for (int kc = 0; kc < 8; kc++) {
            uint32_t af[4];
            af[0] = Psw[g * PS_STRIDE + kc * 8 + tig];
            af[1] = Psw[(g + 8) * PS_STRIDE + kc * 8 + tig];
            af[2] = Psw[g * PS_STRIDE + kc * 8 + tig + 4];
            af[3] = Psw[(g + 8) * PS_STRIDE + kc * 8 + tig + 4];
            uint32_t bf[8][2];
#pragma unroll
            for (int nt = 0; nt < 8; nt++) {
                bf[nt][0] = Vs[(kc * 8 + tig) * VS_STRIDE + nt * 8 + g];
                bf[nt][1] = Vs[(kc * 8 + tig + 4) * VS_STRIDE + nt * 8 + g];
            }
#pragma unroll
            for (int nt = 0; nt < 8; nt++)
                mma_tf32(oacc[nt], af, bf[nt]);
        }
    }

    // ---- finalize: l reduce over quad, normalize, write [B,T,C] ----
    l0 += __shfl_xor_sync(0xffffffffu, l0, 1);
    l0 += __shfl_xor_sync(0xffffffffu, l0, 2);
    l1 += __shfl_xor_sync(0xffffffffu, l1, 1);
    l1 += __shfl_xor_sync(0xffffffffu, l1, 2);
    const float inv0 = 1.0f / l0;
    const float inv1 = 1.0f / l1;

    float* y0 = &g_Y[((size_t)(b * Td + qrow0)) * Cd + h * HSd];
    float* y1 = &g_Y[((size_t)(b * Td + qrow1)) * Cd + h * HSd];
#pragma unroll
    for (int nt = 0; nt < 8; nt++) {
        const int c = nt * 8 + 2 * tig;
        float2 v0, v1;
        v0.x = oacc[nt][0] * inv0; v0.y = oacc[nt][1] * inv0;
        v1.x = oacc[nt][2] * inv1; v1.y = oacc[nt][3] * inv1;
        *(float2*)&y0[c] = v0;
        *(float2*)&y1[c] = v1;
    }
}

// ---------------- launch ----------------------------------------------------
extern "C" void kernel_launch(void* const* d_in, const int* in_sizes, int n_in,
                              void* d_out, int out_size)
{
    const float* x      = (const float*)d_in[0];
    const float* W_attn = (const float*)d_in[1];
    const float* b_attn = (const float*)d_in[2];
    const float* W_proj = (const float*)d_in[3];
    const float* b_proj = (const float*)d_in[4];
    float* out = (float*)d_out;

    (void)in_sizes; (void)n_in; (void)out_size;

    dim3 gQKV(N_QKV / BN, Md / BM);       // (24, 64)
    gemm_tf32_kernel<N_QKV, true, false><<<gQKV, 256>>>(x, W_attn, b_attn, nullptr);

    cudaFuncSetAttribute(attn_mma_kernel,
                         cudaFuncAttributeMaxDynamicSharedMemorySize,
                         ATTN_SMEM_BYTES);
    dim3 gAtt(Td / 128, NHd, Bd);         // (16, 16, 4)
    attn_mma_kernel<<<gAtt, 256, ATTN_SMEM_BYTES>>>();

    dim3 gProj(Cd / BN, Md / BM);         // (8, 64)
    gemm_tf32_kernel<Cd, false, true><<<gProj, 256>>>(nullptr, W_proj, b_proj, out);
}

// round 6
// speedup vs baseline: 3.1784x; 1.7274x over previous
#include <cuda_runtime.h>
#include <cuda_bf16.h>
#include <math.h>
#include <stdint.h>

// Problem constants
#define Bd   4
#define Td   2048
#define Cd   1024
#define NHd  16
#define HSd  64
#define Md   (Bd * Td)          // 8192 rows
#define N_QKV (3 * Cd)          // 3072
#define KDIM Cd                 // 1024

// ---------------- scratch (device globals: allocation-free) ----------------
// All inter-kernel tensors live as tf32 bit patterns (uint32).
__device__ uint32_t g_Q[Bd * NHd * Td * HSd];   // [B,NH,T,HS], pre-scaled 0.125
__device__ uint32_t g_K[Bd * NHd * Td * HSd];
__device__ uint32_t g_V[Bd * NHd * Td * HSd];
__device__ uint32_t g_Y[Md * Cd];               // attention out, [B,T,C]
__device__ uint32_t g_xT[Md * KDIM];            // tf32(x)
__device__ uint32_t g_WA[KDIM * N_QKV];         // tf32(W_attn)
__device__ uint32_t g_WP[KDIM * Cd];            // tf32(W_proj)

// ---------------- TF32 helpers ----------------------------------------------
__device__ __forceinline__ uint32_t f2tf32(float f) {
    uint32_t r;
    asm("cvt.rna.tf32.f32 %0, %1;" : "=r"(r) : "f"(f));
    return r;
}

__device__ __forceinline__ void mma_tf32(float c[4], const uint32_t a[4],
                                         const uint32_t b[2]) {
    asm volatile(
        "mma.sync.aligned.m16n8k8.row.col.f32.tf32.tf32.f32 "
        "{%0,%1,%2,%3}, {%4,%5,%6,%7}, {%8,%9}, {%0,%1,%2,%3};"
        : "+f"(c[0]), "+f"(c[1]), "+f"(c[2]), "+f"(c[3])
        : "r"(a[0]), "r"(a[1]), "r"(a[2]), "r"(a[3]), "r"(b[0]), "r"(b[1]));
}

__device__ __forceinline__ void cp16(uint32_t dst_smem, const void* src) {
    asm volatile("cp.async.cg.shared.global [%0], [%1], 16;\n"
                 :: "r"(dst_smem), "l"(src));
}
#define CP_COMMIT() asm volatile("cp.async.commit_group;\n" ::: "memory")
#define CP_WAIT1()  asm volatile("cp.async.wait_group 1;\n" ::: "memory")
#define CP_WAIT0()  asm volatile("cp.async.wait_group 0;\n" ::: "memory")

// ---------------- convert kernels (fp32 -> tf32 bits, one-time) -------------
__global__ void cvt_kernel(const float4* __restrict__ src, int n4, int which)
{
    uint4* dst = (which == 0) ? (uint4*)g_xT
               : (which == 1) ? (uint4*)g_WA : (uint4*)g_WP;
    for (int i = blockIdx.x * blockDim.x + threadIdx.x; i < n4;
         i += gridDim.x * blockDim.x) {
        float4 v = src[i];
        uint4 u;
        u.x = f2tf32(v.x); u.y = f2tf32(v.y);
        u.z = f2tf32(v.z); u.w = f2tf32(v.w);
        dst[i] = u;
    }
}

// ---------------- TF32 GEMM: cp.async double-buffered -----------------------
// 128x128 tile, BK=16, 256 thr = 8 warps, warp tile 32x64 (2x8 mma m16n8k8)
// A row-major in SMEM stride 20 (conflict-free for (g,tig) fragment reads),
// B k-major stride 136 (conflict-free).

#define BM 128
#define BN 128
#define BK 16
#define ASTR 20
#define BSTR 136

template <int NDIM, bool QKV>
__global__ __launch_bounds__(256)
void gemm_cp_kernel(const float* __restrict__ bias,  // [NDIM]
                    float* __restrict__ out)          // proj only
{
    const uint32_t* A  = QKV ? g_xT : g_Y;
    const uint32_t* Bm = QKV ? g_WA : g_WP;

    __shared__ uint32_t As[2][BM * ASTR];
    __shared__ uint32_t Bs[2][BK * BSTR];

    const int tid = threadIdx.x;
    const int lane = tid & 31;
    const int wid = tid >> 5;
    const int warpM = wid & 3;
    const int warpN = wid >> 2;
    const int g   = lane >> 2;
    const int tig = lane & 3;

    const int rowBase = blockIdx.y * BM;
    const int colBase = blockIdx.x * BN;

    const uint32_t asB = (uint32_t)__cvta_generic_to_shared(&As[0][0]);
    const uint32_t bsB = (uint32_t)__cvta_generic_to_shared(&Bs[0][0]);
    const uint32_t asSz = BM * ASTR * 4;
    const uint32_t bsSz = BK * BSTR * 4;

    // per-thread cp.async segments: 2 for A (512 total), 2 for B (512 total)
    const int s0 = tid * 2;
    const int am0 = s0 >> 2,        ac0 = (s0 & 3) << 2;
    const int am1 = (s0+1) >> 2,    ac1 = ((s0+1) & 3) << 2;
    const int bk0 = s0 >> 5,        bc0 = (s0 & 31) << 2;
    const int bk1 = (s0+1) >> 5,    bc1 = ((s0+1) & 31) << 2;

    const uint32_t aDst0 = asB + (am0 * ASTR + ac0) * 4;
    const uint32_t aDst1 = asB + (am1 * ASTR + ac1) * 4;
    const uint32_t bDst0 = bsB + (bk0 * BSTR + bc0) * 4;
    const uint32_t bDst1 = bsB + (bk1 * BSTR + bc1) * 4;

    const uint32_t* aSrc0 = &A[(size_t)(rowBase + am0) * KDIM + ac0];
    const uint32_t* aSrc1 = &A[(size_t)(rowBase + am1) * KDIM + ac1];
    const uint32_t* bSrc0 = &Bm[(size_t)bk0 * NDIM + colBase + bc0];
    const uint32_t* bSrc1 = &Bm[(size_t)bk1 * NDIM + colBase + bc1];

    float acc[2][8][4];
#pragma unroll
    for (int mt = 0; mt < 2; mt++)
#pragma unroll
        for (int nt = 0; nt < 8; nt++)
#pragma unroll
            for (int i = 0; i < 4; i++) acc[mt][nt][i] = 0.f;

    const int NT = KDIM / BK;   // 64

    // prologue: tile 0 -> buf 0
    cp16(aDst0, aSrc0);
    cp16(aDst1, aSrc1);
    cp16(bDst0, bSrc0);
    cp16(bDst1, bSrc1);
    CP_COMMIT();

    for (int kt = 0; kt < NT; kt++) {
        const int cur = kt & 1;
        if (kt + 1 < NT) {
            const int nxt = 1 - cur;
            const int k0 = (kt + 1) * BK;
            cp16(aDst0 + nxt * asSz, aSrc0 + k0);
            cp16(aDst1 + nxt * asSz, aSrc1 + k0);
            cp16(bDst0 + nxt * bsSz, bSrc0 + (size_t)k0 * NDIM);
            cp16(bDst1 + nxt * bsSz, bSrc1 + (size_t)k0 * NDIM);
            CP_COMMIT();
            CP_WAIT1();
        } else {
            CP_WAIT0();
        }
        __syncthreads();

        const uint32_t* Asb = &As[cur][0];
        const uint32_t* Bsb = &Bs[cur][0];

#pragma unroll
        for (int ks = 0; ks < BK; ks += 8) {
            uint32_t af[2][4];
            uint32_t bf[8][2];
#pragma unroll
            for (int mt = 0; mt < 2; mt++) {
                const int m0 = warpM * 32 + mt * 16 + g;
                af[mt][0] = Asb[m0 * ASTR + ks + tig];
                af[mt][1] = Asb[(m0 + 8) * ASTR + ks + tig];
                af[mt][2] = Asb[m0 * ASTR + ks + tig + 4];
                af[mt][3] = Asb[(m0 + 8) * ASTR + ks + tig + 4];
            }
#pragma unroll
            for (int nt = 0; nt < 8; nt++) {
                const int n0 = warpN * 64 + nt * 8 + g;
                bf[nt][0] = Bsb[(ks + tig) * BSTR + n0];
                bf[nt][1] = Bsb[(ks + tig + 4) * BSTR + n0];
            }
#pragma unroll
            for (int mt = 0; mt < 2; mt++)
#pragma unroll
                for (int nt = 0; nt < 8; nt++)
                    mma_tf32(acc[mt][nt], af[mt], bf[nt]);
        }
        __syncthreads();
    }

    // ---------------- epilogue ----------------
#pragma unroll
    for (int mt = 0; mt < 2; mt++) {
        const int r0 = rowBase + warpM * 32 + mt * 16 + g;
        const int r1 = r0 + 8;
#pragma unroll
        for (int nt = 0; nt < 8; nt++) {
            const int c = colBase + warpN * 64 + nt * 8 + 2 * tig;
            const float b0 = bias[c];
            const float b1 = bias[c + 1];
            if (QKV) {
#pragma unroll
                for (int e = 0; e < 4; e++) {
                    const int r  = (e < 2) ? r0 : r1;
                    const int cc = c + (e & 1);
                    float val = acc[mt][nt][e] + ((e & 1) ? b1 : b0);
                    const int bb = r / Td;
                    const int t  = r % Td;
                    const int which = cc / Cd;
                    const int inner = cc % Cd;
                    const int h = inner / HSd;
                    const int d = inner % HSd;
                    if (which == 0) val *= 0.125f;   // fold softmax scale into Q
                    uint32_t* dst = (which == 0) ? g_Q : (which == 1) ? g_K : g_V;
                    dst[((bb * NHd + h) * Td + t) * HSd + d] = f2tf32(val);
                }
            } else {
                float2 v0, v1;
                v0.x = acc[mt][nt][0] + b0;
                v0.y = acc[mt][nt][1] + b1;
                v1.x = acc[mt][nt][2] + b0;
                v1.y = acc[mt][nt][3] + b1;
                *(float2*)&out[r0 * NDIM + c] = v0;
                *(float2*)&out[r1 * NDIM + c] = v1;
            }
        }
    }
}

// ---------------- tensor-core flash attention (R4 structure, raw tf32 IO) ---
#define KS_STRIDE 68
#define VS_STRIDE 72
#define PS_STRIDE 68
#define SMEM_KS_U   (64 * KS_STRIDE)
#define SMEM_VS_U   (64 * VS_STRIDE)
#define SMEM_PS_U   (8 * 16 * PS_STRIDE)
#define ATTN_SMEM_BYTES ((SMEM_KS_U + SMEM_VS_U + SMEM_PS_U) * 4)  // 70656

__global__ __launch_bounds__(256)
void attn_mma_kernel()
{
    extern __shared__ uint32_t smem[];
    uint32_t* Ks = smem;
    uint32_t* Vs = smem + SMEM_KS_U;
    uint32_t* Ps = smem + SMEM_KS_U + SMEM_VS_U;
    uint32_t* Qs = Ps;   // aliased with P buffer

    const int b = blockIdx.z;
    const int h = blockIdx.y;
    const int qbase = blockIdx.x * 128;

    const int tid  = threadIdx.x;
    const int lane = tid & 31;
    const int w    = tid >> 5;
    const int g    = lane >> 2;
    const int tig  = lane & 3;

    const size_t headOff = (size_t)(b * NHd + h) * Td * HSd;
    const uint32_t* Kg = &g_K[headOff];
    const uint32_t* Vg = &g_V[headOff];
    const uint32_t* Qg = &g_Q[headOff + (size_t)qbase * HSd];

    // ---- stage Q (already tf32, pre-scaled) ----
#pragma unroll
    for (int j = 0; j < 8; j++) {
        const int f = tid + j * 256;
        const int r = f >> 4;
        const int c4 = (f & 15) << 2;
        *(uint4*)&Qs[r * PS_STRIDE + c4] = *(const uint4*)&Qg[r * HSd + c4];
    }
    __syncthreads();

    const int qr0 = w * 16 + g;
    const int qr1 = qr0 + 8;
    uint32_t qf[8][4];
#pragma unroll
    for (int kc = 0; kc < 8; kc++) {
        qf[kc][0] = Qs[qr0 * PS_STRIDE + kc * 8 + tig];
        qf[kc][1] = Qs[qr1 * PS_STRIDE + kc * 8 + tig];
        qf[kc][2] = Qs[qr0 * PS_STRIDE + kc * 8 + tig + 4];
        qf[kc][3] = Qs[qr1 * PS_STRIDE + kc * 8 + tig + 4];
    }

    const int qrow0 = qbase + qr0;
    const int qrow1 = qbase + qr1;

    float oacc[8][4];
#pragma unroll
    for (int nt = 0; nt < 8; nt++)
#pragma unroll
        for (int e = 0; e < 4; e++) oacc[nt][e] = 0.f;
    float m0 = -1e30f, m1 = -1e30f, l0 = 0.f, l1 = 0.f;

    uint32_t* Psw = Ps + w * 16 * PS_STRIDE;
    const int ntiles = 2 * blockIdx.x + 2;

    for (int t = 0; t < ntiles; t++) {
        __syncthreads();

        const uint32_t* Kt = Kg + t * 64 * HSd;
        const uint32_t* Vt = Vg + t * 64 * HSd;
#pragma unroll
        for (int j = 0; j < 4; j++) {
            const int f = tid + j * 256;
            const int r = f >> 4;
            const int c4 = (f & 15) << 2;
            *(uint4*)&Ks[r * KS_STRIDE + c4] = *(const uint4*)&Kt[r * HSd + c4];
            *(uint4*)&Vs[r * VS_STRIDE + c4] = *(const uint4*)&Vt[r * HSd + c4];
        }
        __syncthreads();

        float sacc[8][4];
#pragma unroll
        for (int nt = 0; nt < 8; nt++)
#pragma unroll
            for (int e = 0; e < 4; e++) sacc[nt][e] = 0.f;

#pragma unroll
        for (int kc = 0; kc < 8; kc++) {
            uint32_t bf[8][2];
#pragma unroll
            for (int nt = 0; nt < 8; nt++) {
                bf[nt][0] = Ks[(nt * 8 + g) * KS_STRIDE + kc * 8 + tig];
                bf[nt][1] = Ks[(nt * 8 + g) * KS_STRIDE + kc * 8 + tig + 4];
            }
#pragma unroll
            for (int nt = 0; nt < 8; nt++)
                mma_tf32(sacc[nt], qf[kc], bf[nt]);
        }

        if (t >= 2 * (int)blockIdx.x) {
            const int colb = t * 64;
#pragma unroll
            for (int nt = 0; nt < 8; nt++) {
                const int c0 = colb + nt * 8 + 2 * tig;
                if (c0     > qrow0) sacc[nt][0] = -1e30f;
                if (c0 + 1 > qrow0) sacc[nt][1] = -1e30f;
                if (c0     > qrow1) sacc[nt][2] = -1e30f;
                if (c0 + 1 > qrow1) sacc[nt][3] = -1e30f;
            }
        }

        float mx0 = -1e30f, mx1 = -1e30f;
#pragma unroll
        for (int nt = 0; nt < 8; nt++) {
            mx0 = fmaxf(mx0, fmaxf(sacc[nt][0], sacc[nt][1]));
            mx1 = fmaxf(mx1, fmaxf(sacc[nt][2], sacc[nt][3]));
        }
        mx0 = fmaxf(mx0, __shfl_xor_sync(0xffffffffu, mx0, 1));
        mx0 = fmaxf(mx0, __shfl_xor_sync(0xffffffffu, mx0, 2));
        mx1 = fmaxf(mx1, __shfl_xor_sync(0xffffffffu, mx1, 1));
        mx1 = fmaxf(mx1, __shfl_xor_sync(0xffffffffu, mx1, 2));

        const float nm0 = fmaxf(m0, mx0);
        const float nm1 = fmaxf(m1, mx1);
        const float corr0 = __expf(m0 - nm0);
        const float corr1 = __expf(m1 - nm1);
        m0 = nm0; m1 = nm1;

        float sum0 = 0.f, sum1 = 0.f;
#pragma unroll
        for (int nt = 0; nt < 8; nt++) {
            const float p0 = __expf(sacc[nt][0] - nm0);
            const float p1 = __expf(sacc[nt][1] - nm0);
            const float p2 = __expf(sacc[nt][2] - nm1);
            const float p3 = __expf(sacc[nt][3] - nm1);
            sum0 += p0 + p1;
            sum1 += p2 + p3;
            uint2 u0; u0.x = f2tf32(p0); u0.y = f2tf32(p1);
            uint2 u1; u1.x = f2tf32(p2); u1.y = f2tf32(p3);
            *(uint2*)&Psw[g * PS_STRIDE + nt * 8 + 2 * tig] = u0;
            *(uint2*)&Psw[(g + 8) * PS_STRIDE + nt * 8 + 2 * tig] = u1;
            oacc[nt][0] *= corr0; oacc[nt][1] *= corr0;
            oacc[nt][2] *= corr1; oacc[nt][3] *= corr1;
        }
        l0 = l0 * corr0 + sum0;
        l1 = l1 * corr1 + sum1;
        __syncwarp();

#pragma unroll
        for (int kc = 0; kc < 8; kc++) {
            uint32_t af[4];
            af[0] = Psw[g * PS_STRIDE + kc * 8 + tig];
            af[1] = Psw[(g + 8) * PS_STRIDE + kc * 8 + tig];
            af[2] = Psw[g * PS_STRIDE + kc * 8 + tig + 4];
            af[3] = Psw[(g + 8) * PS_STRIDE + kc * 8 + tig + 4];
            uint32_t bf[8][2];
#pragma unroll
            for (int nt = 0; nt < 8; nt++) {
                bf[nt][0] = Vs[(kc * 8 + tig) * VS_STRIDE + nt * 8 + g];
                bf[nt][1] = Vs[(kc * 8 + tig + 4) * VS_STRIDE + nt * 8 + g];
            }
#pragma unroll
            for (int nt = 0; nt < 8; nt++)
                mma_tf32(oacc[nt], af, bf[nt]);
        }
    }

    l0 += __shfl_xor_sync(0xffffffffu, l0, 1);
    l0 += __shfl_xor_sync(0xffffffffu, l0, 2);
    l1 += __shfl_xor_sync(0xffffffffu, l1, 1);
    l1 += __shfl_xor_sync(0xffffffffu, l1, 2);
    const float inv0 = 1.0f / l0;
    const float inv1 = 1.0f / l1;

    uint32_t* y0 = &g_Y[((size_t)(b * Td + qrow0)) * Cd + h * HSd];
    uint32_t* y1 = &g_Y[((size_t)(b * Td + qrow1)) * Cd + h * HSd];
#pragma unroll
    for (int nt = 0; nt < 8; nt++) {
        const int c = nt * 8 + 2 * tig;
        uint2 v0, v1;
        v0.x = f2tf32(oacc[nt][0] * inv0);
        v0.y = f2tf32(oacc[nt][1] * inv0);
        v1.x = f2tf32(oacc[nt][2] * inv1);
        v1.y = f2tf32(oacc[nt][3] * inv1);
        *(uint2*)&y0[c] = v0;
        *(uint2*)&y1[c] = v1;
    }
}

// ---------------- launch ----------------------------------------------------
extern "C" void kernel_launch(void* const* d_in, const int* in_sizes, int n_in,
                              void* d_out, int out_size)
{
    const float* x      = (const float*)d_in[0];
    const float* W_attn = (const float*)d_in[1];
    const float* b_attn = (const float*)d_in[2];
    const float* W_proj = (const float*)d_in[3];
    const float* b_proj = (const float*)d_in[4];
    float* out = (float*)d_out;

    (void)in_sizes; (void)n_in; (void)out_size;

    // one-time tf32 conversion of inputs/weights
    cvt_kernel<<<4096, 256>>>((const float4*)x,      Md * KDIM / 4,   0);
    cvt_kernel<<<4096, 256>>>((const float4*)W_attn, KDIM * N_QKV / 4, 1);
    cvt_kernel<<<2048, 256>>>((const float4*)W_proj, KDIM * Cd / 4,   2);

    dim3 gQKV(N_QKV / BN, Md / BM);       // (24, 64)
    gemm_cp_kernel<N_QKV, true><<<gQKV, 256>>>(b_attn, nullptr);

    cudaFuncSetAttribute(attn_mma_kernel,
                         cudaFuncAttributeMaxDynamicSharedMemorySize,
                         ATTN_SMEM_BYTES);
    dim3 gAtt(Td / 128, NHd, Bd);         // (16, 16, 4)
    attn_mma_kernel<<<gAtt, 256, ATTN_SMEM_BYTES>>>();

    dim3 gProj(Cd / BN, Md / BM);         // (8, 64)
    gemm_cp_kernel<Cd, false><<<gProj, 256>>>(b_proj, out);
}

// round 7
// speedup vs baseline: 3.7354x; 1.1753x over previous
#include <cuda_runtime.h>
#include <cuda_bf16.h>
#include <math.h>
#include <stdint.h>

// Problem constants
#define Bd   4
#define Td   2048
#define Cd   1024
#define NHd  16
#define HSd  64
#define Md   (Bd * Td)          // 8192 rows
#define N_QKV (3 * Cd)          // 3072
#define KDIM Cd                 // 1024

// ---------------- scratch (device globals: allocation-free) ----------------
// All inter-kernel tensors live as tf32 bit patterns (uint32).
__device__ uint32_t g_Q[Bd * NHd * Td * HSd];   // [B,NH,T,HS], pre-scaled 0.125
__device__ uint32_t g_K[Bd * NHd * Td * HSd];
__device__ uint32_t g_V[Bd * NHd * Td * HSd];
__device__ uint32_t g_Y[Md * Cd];               // attention out, [B,T,C]
__device__ uint32_t g_xT[Md * KDIM];            // tf32(x)
__device__ uint32_t g_WA[KDIM * N_QKV];         // tf32(W_attn)
__device__ uint32_t g_WP[KDIM * Cd];            // tf32(W_proj)

// ---------------- TF32 helpers ----------------------------------------------
__device__ __forceinline__ uint32_t f2tf32(float f) {
    uint32_t r;
    asm("cvt.rna.tf32.f32 %0, %1;" : "=r"(r) : "f"(f));
    return r;
}

__device__ __forceinline__ void mma_tf32(float c[4], const uint32_t a[4],
                                         const uint32_t b[2]) {
    asm volatile(
        "mma.sync.aligned.m16n8k8.row.col.f32.tf32.tf32.f32 "
        "{%0,%1,%2,%3}, {%4,%5,%6,%7}, {%8,%9}, {%0,%1,%2,%3};"
        : "+f"(c[0]), "+f"(c[1]), "+f"(c[2]), "+f"(c[3])
        : "r"(a[0]), "r"(a[1]), "r"(a[2]), "r"(a[3]), "r"(b[0]), "r"(b[1]));
}

__device__ __forceinline__ void cp16(uint32_t dst_smem, const void* src) {
    asm volatile("cp.async.cg.shared.global [%0], [%1], 16;\n"
                 :: "r"(dst_smem), "l"(src));
}
#define CP_COMMIT() asm volatile("cp.async.commit_group;\n" ::: "memory")
#define CP_WAIT1()  asm volatile("cp.async.wait_group 1;\n" ::: "memory")
#define CP_WAIT0()  asm volatile("cp.async.wait_group 0;\n" ::: "memory")

// ---------------- convert kernels (fp32 -> tf32 bits, one-time) -------------
__global__ void cvt_kernel(const float4* __restrict__ src, int n4, int which)
{
    uint4* dst = (which == 0) ? (uint4*)g_xT
               : (which == 1) ? (uint4*)g_WA : (uint4*)g_WP;
    for (int i = blockIdx.x * blockDim.x + threadIdx.x; i < n4;
         i += gridDim.x * blockDim.x) {
        float4 v = src[i];
        uint4 u;
        u.x = f2tf32(v.x); u.y = f2tf32(v.y);
        u.z = f2tf32(v.z); u.w = f2tf32(v.w);
        dst[i] = u;
    }
}

// ---------------- TF32 GEMM: cp.async double-buffered, 2 CTAs/SM ------------
// 128x128 tile, BK=16, 256 thr = 8 warps, warp tile 32x64 (2x8 mma m16n8k8)

#define BM 128
#define BN 128
#define BK 16
#define ASTR 20
#define BSTR 136

template <int NDIM, bool QKV>
__global__ __launch_bounds__(256, 2)
void gemm_cp_kernel(const float* __restrict__ bias,  // [NDIM]
                    float* __restrict__ out)          // proj only
{
    const uint32_t* A  = QKV ? g_xT : g_Y;
    const uint32_t* Bm = QKV ? g_WA : g_WP;

    __shared__ uint32_t As[2][BM * ASTR];
    __shared__ uint32_t Bs[2][BK * BSTR];

    const int tid = threadIdx.x;
    const int lane = tid & 31;
    const int wid = tid >> 5;
    const int warpM = wid & 3;
    const int warpN = wid >> 2;
    const int g   = lane >> 2;
    const int tig = lane & 3;

    const int rowBase = blockIdx.y * BM;
    const int colBase = blockIdx.x * BN;

    const uint32_t asB = (uint32_t)__cvta_generic_to_shared(&As[0][0]);
    const uint32_t bsB = (uint32_t)__cvta_generic_to_shared(&Bs[0][0]);
    const uint32_t asSz = BM * ASTR * 4;
    const uint32_t bsSz = BK * BSTR * 4;

    // per-thread cp.async segments: 2 for A (512 total), 2 for B (512 total)
    const int s0 = tid * 2;
    const int am0 = s0 >> 2,        ac0 = (s0 & 3) << 2;
    const int am1 = (s0+1) >> 2,    ac1 = ((s0+1) & 3) << 2;
    const int bk0 = s0 >> 5,        bc0 = (s0 & 31) << 2;
    const int bk1 = (s0+1) >> 5,    bc1 = ((s0+1) & 31) << 2;

    const uint32_t aDst0 = asB + (am0 * ASTR + ac0) * 4;
    const uint32_t aDst1 = asB + (am1 * ASTR + ac1) * 4;
    const uint32_t bDst0 = bsB + (bk0 * BSTR + bc0) * 4;
    const uint32_t bDst1 = bsB + (bk1 * BSTR + bc1) * 4;

    const uint32_t* aSrc0 = &A[(size_t)(rowBase + am0) * KDIM + ac0];
    const uint32_t* aSrc1 = &A[(size_t)(rowBase + am1) * KDIM + ac1];
    const uint32_t* bSrc0 = &Bm[(size_t)bk0 * NDIM + colBase + bc0];
    const uint32_t* bSrc1 = &Bm[(size_t)bk1 * NDIM + colBase + bc1];

    float acc[2][8][4];
#pragma unroll
    for (int mt = 0; mt < 2; mt++)
#pragma unroll
        for (int nt = 0; nt < 8; nt++)
#pragma unroll
            for (int i = 0; i < 4; i++) acc[mt][nt][i] = 0.f;

    const int NT = KDIM / BK;   // 64

    // prologue: tile 0 -> buf 0
    cp16(aDst0, aSrc0);
    cp16(aDst1, aSrc1);
    cp16(bDst0, bSrc0);
    cp16(bDst1, bSrc1);
    CP_COMMIT();

    for (int kt = 0; kt < NT; kt++) {
        const int cur = kt & 1;
        if (kt + 1 < NT) {
            const int nxt = 1 - cur;
            const int k0 = (kt + 1) * BK;
            cp16(aDst0 + nxt * asSz, aSrc0 + k0);
            cp16(aDst1 + nxt * asSz, aSrc1 + k0);
            cp16(bDst0 + nxt * bsSz, bSrc0 + (size_t)k0 * NDIM);
            cp16(bDst1 + nxt * bsSz, bSrc1 + (size_t)k0 * NDIM);
            CP_COMMIT();
            CP_WAIT1();
        } else {
            CP_WAIT0();
        }
        __syncthreads();

        const uint32_t* Asb = &As[cur][0];
        const uint32_t* Bsb = &Bs[cur][0];

#pragma unroll
        for (int ks = 0; ks < BK; ks += 8) {
            uint32_t af[2][4];
            uint32_t bf[8][2];
#pragma unroll
            for (int mt = 0; mt < 2; mt++) {
                const int m0 = warpM * 32 + mt * 16 + g;
                af[mt][0] = Asb[m0 * ASTR + ks + tig];
                af[mt][1] = Asb[(m0 + 8) * ASTR + ks + tig];
                af[mt][2] = Asb[m0 * ASTR + ks + tig + 4];
                af[mt][3] = Asb[(m0 + 8) * ASTR + ks + tig + 4];
            }
#pragma unroll
            for (int nt = 0; nt < 8; nt++) {
                const int n0 = warpN * 64 + nt * 8 + g;
                bf[nt][0] = Bsb[(ks + tig) * BSTR + n0];
                bf[nt][1] = Bsb[(ks + tig + 4) * BSTR + n0];
            }
#pragma unroll
            for (int mt = 0; mt < 2; mt++)
#pragma unroll
                for (int nt = 0; nt < 8; nt++)
                    mma_tf32(acc[mt][nt], af[mt], bf[nt]);
        }
        __syncthreads();
    }

    // ---------------- epilogue ----------------
#pragma unroll
    for (int mt = 0; mt < 2; mt++) {
        const int r0 = rowBase + warpM * 32 + mt * 16 + g;
        const int r1 = r0 + 8;
#pragma unroll
        for (int nt = 0; nt < 8; nt++) {
            const int c = colBase + warpN * 64 + nt * 8 + 2 * tig;
            const float b0 = bias[c];
            const float b1 = bias[c + 1];
            if (QKV) {
#pragma unroll
                for (int e = 0; e < 4; e++) {
                    const int r  = (e < 2) ? r0 : r1;
                    const int cc = c + (e & 1);
                    float val = acc[mt][nt][e] + ((e & 1) ? b1 : b0);
                    const int bb = r / Td;
                    const int t  = r % Td;
                    const int which = cc / Cd;
                    const int inner = cc % Cd;
                    const int h = inner / HSd;
                    const int d = inner % HSd;
                    if (which == 0) val *= 0.125f;   // fold softmax scale into Q
                    uint32_t* dst = (which == 0) ? g_Q : (which == 1) ? g_K : g_V;
                    dst[((bb * NHd + h) * Td + t) * HSd + d] = f2tf32(val);
                }
            } else {
                float2 v0, v1;
                v0.x = acc[mt][nt][0] + b0;
                v0.y = acc[mt][nt][1] + b1;
                v1.x = acc[mt][nt][2] + b0;
                v1.y = acc[mt][nt][3] + b1;
                *(float2*)&out[r0 * NDIM + c] = v0;
                *(float2*)&out[r1 * NDIM + c] = v1;
            }
        }
    }
}

// ---------------- tensor-core flash attention (unchanged, passing) ----------
#define KS_STRIDE 68
#define VS_STRIDE 72
#define PS_STRIDE 68
#define SMEM_KS_U   (64 * KS_STRIDE)
#define SMEM_VS_U   (64 * VS_STRIDE)
#define SMEM_PS_U   (8 * 16 * PS_STRIDE)
#define ATTN_SMEM_BYTES ((SMEM_KS_U + SMEM_VS_U + SMEM_PS_U) * 4)  // 70656

__global__ __launch_bounds__(256)
void attn_mma_kernel()
{
    extern __shared__ uint32_t smem[];
    uint32_t* Ks = smem;
    uint32_t* Vs = smem + SMEM_KS_U;
    uint32_t* Ps = smem + SMEM_KS_U + SMEM_VS_U;
    uint32_t* Qs = Ps;   // aliased with P buffer

    const int b = blockIdx.z;
    const int h = blockIdx.y;
    const int qbase = blockIdx.x * 128;

    const int tid  = threadIdx.x;
    const int lane = tid & 31;
    const int w    = tid >> 5;
    const int g    = lane >> 2;
    const int tig  = lane & 3;

    const size_t headOff = (size_t)(b * NHd + h) * Td * HSd;
    const uint32_t* Kg = &g_K[headOff];
    const uint32_t* Vg = &g_V[headOff];
    const uint32_t* Qg = &g_Q[headOff + (size_t)qbase * HSd];

    // ---- stage Q (already tf32, pre-scaled) ----
#pragma unroll
    for (int j = 0; j < 8; j++) {
        const int f = tid + j * 256;
        const int r = f >> 4;
        const int c4 = (f & 15) << 2;
        *(uint4*)&Qs[r * PS_STRIDE + c4] = *(const uint4*)&Qg[r * HSd + c4];
    }
    __syncthreads();

    const int qr0 = w * 16 + g;
    const int qr1 = qr0 + 8;
    uint32_t qf[8][4];
#pragma unroll
    for (int kc = 0; kc < 8; kc++) {
        qf[kc][0] = Qs[qr0 * PS_STRIDE + kc * 8 + tig];
        qf[kc][1] = Qs[qr1 * PS_STRIDE + kc * 8 + tig];
        qf[kc][2] = Qs[qr0 * PS_STRIDE + kc * 8 + tig + 4];
        qf[kc][3] = Qs[qr1 * PS_STRIDE + kc * 8 + tig + 4];
    }

    const int qrow0 = qbase + qr0;
    const int qrow1 = qbase + qr1;

    float oacc[8][4];
#pragma unroll
    for (int nt = 0; nt < 8; nt++)
#pragma unroll
        for (int e = 0; e < 4; e++) oacc[nt][e] = 0.f;
    float m0 = -1e30f, m1 = -1e30f, l0 = 0.f, l1 = 0.f;

    uint32_t* Psw = Ps + w * 16 * PS_STRIDE;
    const int ntiles = 2 * blockIdx.x + 2;

    for (int t = 0; t < ntiles; t++) {
        __syncthreads();

        const uint32_t* Kt = Kg + t * 64 * HSd;
        const uint32_t* Vt = Vg + t * 64 * HSd;
#pragma unroll
        for (int j = 0; j < 4; j++) {
            const int f = tid + j * 256;
            const int r = f >> 4;
            const int c4 = (f & 15) << 2;
            *(uint4*)&Ks[r * KS_STRIDE + c4] = *(const uint4*)&Kt[r * HSd + c4];
            *(uint4*)&Vs[r * VS_STRIDE + c4] = *(const uint4*)&Vt[r * HSd + c4];
        }
        __syncthreads();

        float sacc[8][4];
#pragma unroll
        for (int nt = 0; nt < 8; nt++)
#pragma unroll
            for (int e = 0; e < 4; e++) sacc[nt][e] = 0.f;

#pragma unroll
        for (int kc = 0; kc < 8; kc++) {
            uint32_t bf[8][2];
#pragma unroll
            for (int nt = 0; nt < 8; nt++) {
                bf[nt][0] = Ks[(nt * 8 + g) * KS_STRIDE + kc * 8 + tig];
                bf[nt][1] = Ks[(nt * 8 + g) * KS_STRIDE + kc * 8 + tig + 4];
            }
#pragma unroll
            for (int nt = 0; nt < 8; nt++)
                mma_tf32(sacc[nt], qf[kc], bf[nt]);
        }

        if (t >= 2 * (int)blockIdx.x) {
            const int colb = t * 64;
#pragma unroll
            for (int nt = 0; nt < 8; nt++) {
                const int c0 = colb + nt * 8 + 2 * tig;
                if (c0     > qrow0) sacc[nt][0] = -1e30f;
                if (c0 + 1 > qrow0) sacc[nt][1] = -1e30f;
                if (c0     > qrow1) sacc[nt][2] = -1e30f;
                if (c0 + 1 > qrow1) sacc[nt][3] = -1e30f;
            }
        }

        float mx0 = -1e30f, mx1 = -1e30f;
#pragma unroll
        for (int nt = 0; nt < 8; nt++) {
            mx0 = fmaxf(mx0, fmaxf(sacc[nt][0], sacc[nt][1]));
            mx1 = fmaxf(mx1, fmaxf(sacc[nt][2], sacc[nt][3]));
        }
        mx0 = fmaxf(mx0, __shfl_xor_sync(0xffffffffu, mx0, 1));
        mx0 = fmaxf(mx0, __shfl_xor_sync(0xffffffffu, mx0, 2));
        mx1 = fmaxf(mx1, __shfl_xor_sync(0xffffffffu, mx1, 1));
        mx1 = fmaxf(mx1, __shfl_xor_sync(0xffffffffu, mx1, 2));

        const float nm0 = fmaxf(m0, mx0);
        const float nm1 = fmaxf(m1, mx1);
        const float corr0 = __expf(m0 - nm0);
        const float corr1 = __expf(m1 - nm1);
        m0 = nm0; m1 = nm1;

        float sum0 = 0.f, sum1 = 0.f;
#pragma unroll
        for (int nt = 0; nt < 8; nt++) {
            const float p0 = __expf(sacc[nt][0] - nm0);
            const float p1 = __expf(sacc[nt][1] - nm0);
            const float p2 = __expf(sacc[nt][2] - nm1);
            const float p3 = __expf(sacc[nt][3] - nm1);
            sum0 += p0 + p1;
            sum1 += p2 + p3;
            uint2 u0; u0.x = f2tf32(p0); u0.y = f2tf32(p1);
            uint2 u1; u1.x = f2tf32(p2); u1.y = f2tf32(p3);
            *(uint2*)&Psw[g * PS_STRIDE + nt * 8 + 2 * tig] = u0;
            *(uint2*)&Psw[(g + 8) * PS_STRIDE + nt * 8 + 2 * tig] = u1;
            oacc[nt][0] *= corr0; oacc[nt][1] *= corr0;
            oacc[nt][2] *= corr1; oacc[nt][3] *= corr1;
        }
        l0 = l0 * corr0 + sum0;
        l1 = l1 * corr1 + sum1;
        __syncwarp();

#pragma unroll
        for (int kc = 0; kc < 8; kc++) {
            uint32_t af[4];
            af[0] = Psw[g * PS_STRIDE + kc * 8 + tig];
            af[1] = Psw[(g + 8) * PS_STRIDE + kc * 8 + tig];
            af[2] = Psw[g * PS_STRIDE + kc * 8 + tig + 4];
            af[3] = Psw[(g + 8) * PS_STRIDE + kc * 8 + tig + 4];
            uint32_t bf[8][2];
#pragma unroll
            for (int nt = 0; nt < 8; nt++) {
                bf[nt][0] = Vs[(kc * 8 + tig) * VS_STRIDE + nt * 8 + g];
                bf[nt][1] = Vs[(kc * 8 + tig + 4) * VS_STRIDE + nt * 8 + g];
            }
#pragma unroll
            for (int nt = 0; nt < 8; nt++)
                mma_tf32(oacc[nt], af, bf[nt]);
        }
    }

    l0 += __shfl_xor_sync(0xffffffffu, l0, 1);
    l0 += __shfl_xor_sync(0xffffffffu, l0, 2);
    l1 += __shfl_xor_sync(0xffffffffu, l1, 1);
    l1 += __shfl_xor_sync(0xffffffffu, l1, 2);
    const float inv0 = 1.0f / l0;
    const float inv1 = 1.0f / l1;

    uint32_t* y0 = &g_Y[((size_t)(b * Td + qrow0)) * Cd + h * HSd];
    uint32_t* y1 = &g_Y[((size_t)(b * Td + qrow1)) * Cd + h * HSd];
#pragma unroll
    for (int nt = 0; nt < 8; nt++) {
        const int c = nt * 8 + 2 * tig;
        uint2 v0, v1;
        v0.x = f2tf32(oacc[nt][0] * inv0);
        v0.y = f2tf32(oacc[nt][1] * inv0);
        v1.x = f2tf32(oacc[nt][2] * inv1);
        v1.y = f2tf32(oacc[nt][3] * inv1);
        *(uint2*)&y0[c] = v0;
        *(uint2*)&y1[c] = v1;
    }
}

// ---------------- launch ----------------------------------------------------
extern "C" void kernel_launch(void* const* d_in, const int* in_sizes, int n_in,
                              void* d_out, int out_size)
{
    const float* x      = (const float*)d_in[0];
    const float* W_attn = (const float*)d_in[1];
    const float* b_attn = (const float*)d_in[2];
    const float* W_proj = (const float*)d_in[3];
    const float* b_proj = (const float*)d_in[4];
    float* out = (float*)d_out;

    (void)in_sizes; (void)n_in; (void)out_size;

    // one-time tf32 conversion of inputs/weights
    cvt_kernel<<<4096, 256>>>((const float4*)x,      Md * KDIM / 4,   0);
    cvt_kernel<<<4096, 256>>>((const float4*)W_attn, KDIM * N_QKV / 4, 1);
    cvt_kernel<<<2048, 256>>>((const float4*)W_proj, KDIM * Cd / 4,   2);

    dim3 gQKV(N_QKV / BN, Md / BM);       // (24, 64)
    gemm_cp_kernel<N_QKV, true><<<gQKV, 256>>>(b_attn, nullptr);

    cudaFuncSetAttribute(attn_mma_kernel,
                         cudaFuncAttributeMaxDynamicSharedMemorySize,
                         ATTN_SMEM_BYTES);
    dim3 gAtt(Td / 128, NHd, Bd);         // (16, 16, 4)
    attn_mma_kernel<<<gAtt, 256, ATTN_SMEM_BYTES>>>();

    dim3 gProj(Cd / BN, Md / BM);         // (8, 64)
    gemm_cp_kernel<Cd, false><<<gProj, 256>>>(b_proj, out);
}

// round 10
// speedup vs baseline: 7.2459x; 1.9398x over previous
#include <cuda_runtime.h>
#include <cuda_fp16.h>
#include <math.h>
#include <stdint.h>

// Problem constants
#define Bd   4
#define Td   2048
#define Cd   1024
#define NHd  16
#define HSd  64
#define Md   (Bd * Td)          // 8192 rows
#define N_QKV (3 * Cd)          // 3072
#define KDIM Cd                 // 1024

// ---------------- scratch (device globals: allocation-free) ----------------
// All inter-kernel tensors are fp16.
__device__ __align__(16) __half g_Q[Bd * NHd * Td * HSd];  // pre-scaled 0.125
__device__ __align__(16) __half g_K[Bd * NHd * Td * HSd];
__device__ __align__(16) __half g_V[Bd * NHd * Td * HSd];
__device__ __align__(16) __half g_Y[Md * Cd];              // attn out [B,T,C]
__device__ __align__(16) __half g_xh[Md * KDIM];           // fp16(x)
__device__ __align__(16) __half g_WAh[KDIM * N_QKV];       // fp16(W_attn)
__device__ __align__(16) __half g_WPh[KDIM * Cd];          // fp16(W_proj)

// ---------------- helpers ----------------------------------------------------
__device__ __forceinline__ uint32_t smem_u32(const void* p) {
    return (uint32_t)__cvta_generic_to_shared(p);
}

__device__ __forceinline__ uint32_t h2_bits(__half2 h) {
    return *reinterpret_cast<uint32_t*>(&h);
}

__device__ __forceinline__ void ldm_x4(uint32_t r[4], uint32_t addr) {
    asm volatile("ldmatrix.sync.aligned.m8n8.x4.shared.b16 {%0,%1,%2,%3}, [%4];"
                 : "=r"(r[0]), "=r"(r[1]), "=r"(r[2]), "=r"(r[3]) : "r"(addr));
}
__device__ __forceinline__ void ldm_x2(uint32_t& r0, uint32_t& r1, uint32_t addr) {
    asm volatile("ldmatrix.sync.aligned.m8n8.x2.shared.b16 {%0,%1}, [%2];"
                 : "=r"(r0), "=r"(r1) : "r"(addr));
}
__device__ __forceinline__ void ldm_x2t(uint32_t& r0, uint32_t& r1, uint32_t addr) {
    asm volatile("ldmatrix.sync.aligned.m8n8.x2.trans.shared.b16 {%0,%1}, [%2];"
                 : "=r"(r0), "=r"(r1) : "r"(addr));
}

__device__ __forceinline__ void mma_f16(float c[4], const uint32_t a[4],
                                        const uint32_t b[2]) {
    asm volatile(
        "mma.sync.aligned.m16n8k16.row.col.f32.f16.f16.f32 "
        "{%0,%1,%2,%3}, {%4,%5,%6,%7}, {%8,%9}, {%0,%1,%2,%3};"
        : "+f"(c[0]), "+f"(c[1]), "+f"(c[2]), "+f"(c[3])
        : "r"(a[0]), "r"(a[1]), "r"(a[2]), "r"(a[3]), "r"(b[0]), "r"(b[1]));
}

__device__ __forceinline__ void cp16(uint32_t dst_smem, const void* src) {
    asm volatile("cp.async.cg.shared.global [%0], [%1], 16;\n"
                 :: "r"(dst_smem), "l"(src));
}
#define CP_COMMIT() asm volatile("cp.async.commit_group;\n" ::: "memory")
#define CP_WAIT1()  asm volatile("cp.async.wait_group 1;\n" ::: "memory")
#define CP_WAIT0()  asm volatile("cp.async.wait_group 0;\n" ::: "memory")

// ---------------- convert kernels (fp32 -> fp16, one-time) -------------------
__global__ void cvt_kernel(const float4* __restrict__ src, int n4, int which)
{
    uint2* dst = (which == 0) ? (uint2*)g_xh
               : (which == 1) ? (uint2*)g_WAh : (uint2*)g_WPh;
    for (int i = blockIdx.x * blockDim.x + threadIdx.x; i < n4;
         i += gridDim.x * blockDim.x) {
        float4 v = src[i];
        uint2 u;
        u.x = h2_bits(__floats2half2_rn(v.x, v.y));
        u.y = h2_bits(__floats2half2_rn(v.z, v.w));
        dst[i] = u;
    }
}

__device__ __forceinline__ uint32_t pack_h2(float a, float b) {
    return h2_bits(__floats2half2_rn(a, b));
}

// ---------------- FP16 GEMM: cp.async double-buffered, ldmatrix -------------
// 128x128 tile, BK=32 halves, 256 thr = 8 warps, warp tile 32x64
// (2mt x 8nt of m16n8k16).  ASTRH=40, BSTRH=136 (stride/8 odd => ldmatrix
// conflict-free).

#define BM 128
#define BN 128
#define BKH 32
#define ASTRH 40
#define BSTRH 136

template <int NDIM, bool QKV>
__global__ __launch_bounds__(256, 2)
void gemm_f16_kernel(const float* __restrict__ bias,  // [NDIM]
                     float* __restrict__ out)          // proj only
{
    const __half* A  = QKV ? g_xh : g_Y;
    const __half* Bm = QKV ? g_WAh : g_WPh;

    __shared__ __half As[2][BM * ASTRH];
    __shared__ __half Bs[2][BKH * BSTRH];

    const int tid = threadIdx.x;
    const int lane = tid & 31;
    const int wid = tid >> 5;
    const int warpM = wid & 3;
    const int warpN = wid >> 2;
    const int g   = lane >> 2;
    const int tig = lane & 3;

    const int rowBase = blockIdx.y * BM;
    const int colBase = blockIdx.x * BN;

    const uint32_t asB = smem_u32(&As[0][0]);
    const uint32_t bsB = smem_u32(&Bs[0][0]);
    const uint32_t ASZ = BM * ASTRH * 2;
    const uint32_t BSZ = BKH * BSTRH * 2;

    // cp.async staging: A 512 chunks (16B), B 512 chunks; 2 each per thread
    const int mA = tid >> 1;
    const int cA = (tid & 1) << 1;          // chunks cA, cA+1 (of 4 per row)
    const int kB = tid >> 3;
    const int cB = (tid & 7) << 1;          // chunks cB, cB+1 (of 16 per row)

    const uint32_t aDst0 = asB + (mA * ASTRH + cA * 8) * 2;
    const uint32_t bDst0 = bsB + (kB * BSTRH + cB * 8) * 2;
    const __half* aSrc = &A[(size_t)(rowBase + mA) * KDIM + cA * 8];
    const __half* bSrc = &Bm[(size_t)kB * NDIM + colBase + cB * 8];

    // ldmatrix per-lane geometry
    const int mat4 = lane >> 3;
    const int rA   = ((mat4 & 1) << 3) + (lane & 7);   // A row offset
    const int cAq  = (mat4 >> 1) << 3;                 // A col offset
    const int kB16 = lane & 15;                        // B row-within

    float acc[2][8][4];
#pragma unroll
    for (int mt = 0; mt < 2; mt++)
#pragma unroll
        for (int nt = 0; nt < 8; nt++)
#pragma unroll
            for (int i = 0; i < 4; i++) acc[mt][nt][i] = 0.f;

    const int NT = KDIM / BKH;   // 32

    // prologue: tile 0 -> buf 0
    cp16(aDst0,      aSrc);
    cp16(aDst0 + 16, aSrc + 8);
    cp16(bDst0,      bSrc);
    cp16(bDst0 + 16, bSrc + 8);
    CP_COMMIT();

    for (int kt = 0; kt < NT; kt++) {
        const int cur = kt & 1;
        if (kt + 1 < NT) {
            const int nxt = 1 - cur;
            const int k0 = (kt + 1) * BKH;
            cp16(aDst0 + nxt * ASZ,      aSrc + k0);
            cp16(aDst0 + nxt * ASZ + 16, aSrc + k0 + 8);
            cp16(bDst0 + nxt * BSZ,      bSrc + (size_t)k0 * NDIM);
            cp16(bDst0 + nxt * BSZ + 16, bSrc + (size_t)k0 * NDIM + 8);
            CP_COMMIT();
            CP_WAIT1();
        } else {
            CP_WAIT0();
        }
        __syncthreads();

        const uint32_t aB = asB + cur * ASZ;
        const uint32_t bB = bsB + cur * BSZ;

#pragma unroll
        for (int kc = 0; kc < 2; kc++) {
            uint32_t af[2][4];
#pragma unroll
            for (int mt = 0; mt < 2; mt++)
                ldm_x4(af[mt], aB + ((warpM * 32 + mt * 16 + rA) * ASTRH
                                     + kc * 16 + cAq) * 2);
            uint32_t bf[8][2];
#pragma unroll
            for (int nt = 0; nt < 8; nt++)
                ldm_x2t(bf[nt][0], bf[nt][1],
                        bB + ((kc * 16 + kB16) * BSTRH
                              + warpN * 64 + nt * 8) * 2);
#pragma unroll
            for (int mt = 0; mt < 2; mt++)
#pragma unroll
                for (int nt = 0; nt < 8; nt++)
                    mma_f16(acc[mt][nt], af[mt], bf[nt]);
        }
        __syncthreads();
    }

    // ---------------- epilogue ----------------
#pragma unroll
    for (int mt = 0; mt < 2; mt++) {
        const int r0 = rowBase + warpM * 32 + mt * 16 + g;
        const int r1 = r0 + 8;
#pragma unroll
        for (int nt = 0; nt < 8; nt++) {
            const int c = colBase + warpN * 64 + nt * 8 + 2 * tig;
            const float b0 = bias[c];
            const float b1 = bias[c + 1];
            if (QKV) {
                const int which = c / Cd;        // 0=q 1=k 2=v (pair same head)
                const int inner = c % Cd;
                const int h = inner / HSd;
                const int d = inner % HSd;
                const float sc = (which == 0) ? 0.125f : 1.0f;
                __half* dst = (which == 0) ? g_Q : (which == 1) ? g_K : g_V;
                // row r0
                {
                    const int bb = r0 / Td, t = r0 % Td;
                    const size_t idx = ((size_t)(bb * NHd + h) * Td + t) * HSd + d;
                    *(__half2*)&dst[idx] =
                        __floats2half2_rn((acc[mt][nt][0] + b0) * sc,
                                          (acc[mt][nt][1] + b1) * sc);
                }
                // row r1
                {
                    const int bb = r1 / Td, t = r1 % Td;
                    const size_t idx = ((size_t)(bb * NHd + h) * Td + t) * HSd + d;
                    *(__half2*)&dst[idx] =
                        __floats2half2_rn((acc[mt][nt][2] + b0) * sc,
                                          (acc[mt][nt][3] + b1) * sc);
                }
            } else {
                float2 v0, v1;
                v0.x = acc[mt][nt][0] + b0;
                v0.y = acc[mt][nt][1] + b1;
                v1.x = acc[mt][nt][2] + b0;
                v1.y = acc[mt][nt][3] + b1;
                *(float2*)&out[(size_t)r0 * NDIM + c] = v0;
                *(float2*)&out[(size_t)r1 * NDIM + c] = v1;
            }
        }
    }
}

// ---------------- FP16 tensor-core flash attention ---------------------------
// 1 CTA = 128 query rows of one (b,h). 8 warps x 16 rows. 64-key tiles.
// P stays in registers: f16 C-fragment layout == A-fragment layout.

#define QSTRH 72
#define KSTRH 72
#define VSTRH 72

__global__ __launch_bounds__(256, 2)
void attn_f16_kernel()
{
    __shared__ __half Qs[128 * QSTRH];
    __shared__ __half Ks[64 * KSTRH];
    __shared__ __half Vs[64 * VSTRH];

    const int b = blockIdx.z;
    const int h = blockIdx.y;
    const int qbase = blockIdx.x * 128;

    const int tid  = threadIdx.x;
    const int lane = tid & 31;
    const int w    = tid >> 5;
    const int g    = lane >> 2;
    const int tig  = lane & 3;

    const uint32_t qsB = smem_u32(Qs);
    const uint32_t ksB = smem_u32(Ks);
    const uint32_t vsB = smem_u32(Vs);

    const size_t headOff = (size_t)(b * NHd + h) * Td * HSd;
    const __half* Kg = &g_K[headOff];
    const __half* Vg = &g_V[headOff];
    const __half* Qg = &g_Q[headOff + (size_t)qbase * HSd];

    // ---- stage Q (128 x 64 halves) ----
#pragma unroll
    for (int j = 0; j < 4; j++) {
        const int f = tid + j * 256;        // chunk 0..1023
        const int r = f >> 3;
        const int c8 = (f & 7) << 3;
        *(uint4*)&Qs[r * QSTRH + c8] = *(const uint4*)&Qg[r * HSd + c8];
    }
    __syncthreads();

    // ldmatrix lane geometry
    const int mat4 = lane >> 3;
    const int rQ   = w * 16 + ((mat4 & 1) << 3) + (lane & 7);
    const int cQ   = (mat4 >> 1) << 3;
    const int l8   = lane & 7;
    const int mat2 = (lane & 15) >> 3;

    uint32_t qf[4][4];
#pragma unroll
    for (int kc = 0; kc < 4; kc++)
        ldm_x4(qf[kc], qsB + (rQ * QSTRH + kc * 16 + cQ) * 2);

    const int qrow0 = qbase + w * 16 + g;
    const int qrow1 = qrow0 + 8;

    float oacc[8][4];
#pragma unroll
    for (int nt = 0; nt < 8; nt++)
#pragma unroll
        for (int e = 0; e < 4; e++) oacc[nt][e] = 0.f;
    float m0 = -1e30f, m1 = -1e30f, l0 = 0.f, l1 = 0.f;

    const int ntiles = 2 * blockIdx.x + 2;

    for (int t = 0; t < ntiles; t++) {
        __syncthreads();

        // ---- stage K,V (64 x 64 halves each) ----
        const __half* Kt = Kg + t * 64 * HSd;
        const __half* Vt = Vg + t * 64 * HSd;
#pragma unroll
        for (int j = 0; j < 2; j++) {
            const int f = tid + j * 256;    // chunk 0..511
            const int r = f >> 3;
            const int c8 = (f & 7) << 3;
            *(uint4*)&Ks[r * KSTRH + c8] = *(const uint4*)&Kt[r * HSd + c8];
            *(uint4*)&Vs[r * VSTRH + c8] = *(const uint4*)&Vt[r * HSd + c8];
        }
        __syncthreads();

        // ---- S = Q K^T : 16 x 64 per warp ----
        float sacc[8][4];
#pragma unroll
        for (int nt = 0; nt < 8; nt++)
#pragma unroll
            for (int e = 0; e < 4; e++) sacc[nt][e] = 0.f;

#pragma unroll
        for (int kc = 0; kc < 4; kc++) {    // d chunks of 16
#pragma unroll
            for (int nt = 0; nt < 8; nt++) {
                uint32_t kf0, kf1;          // K fragment: non-trans ldmatrix
                ldm_x2(kf0, kf1,
                       ksB + ((nt * 8 + l8) * KSTRH + kc * 16 + mat2 * 8) * 2);
                uint32_t bf[2] = {kf0, kf1};
                mma_f16(sacc[nt], qf[kc], bf);
            }
        }

        // ---- causal mask ----
        if (t >= 2 * (int)blockIdx.x) {
            const int colb = t * 64;
#pragma unroll
            for (int nt = 0; nt < 8; nt++) {
                const int c0 = colb + nt * 8 + 2 * tig;
                if (c0     > qrow0) sacc[nt][0] = -1e30f;
                if (c0 + 1 > qrow0) sacc[nt][1] = -1e30f;
                if (c0     > qrow1) sacc[nt][2] = -1e30f;
                if (c0 + 1 > qrow1) sacc[nt][3] = -1e30f;
            }
        }

        // ---- online softmax ----
        float mx0 = -1e30f, mx1 = -1e30f;
#pragma unroll
        for (int nt = 0; nt < 8; nt++) {
            mx0 = fmaxf(mx0, fmaxf(sacc[nt][0], sacc[nt][1]));
            mx1 = fmaxf(mx1, fmaxf(sacc[nt][2], sacc[nt][3]));
        }
        mx0 = fmaxf(mx0, __shfl_xor_sync(0xffffffffu, mx0, 1));
        mx0 = fmaxf(mx0, __shfl_xor_sync(0xffffffffu, mx0, 2));
        mx1 = fmaxf(mx1, __shfl_xor_sync(0xffffffffu, mx1, 1));
        mx1 = fmaxf(mx1, __shfl_xor_sync(0xffffffffu, mx1, 2));

        const float nm0 = fmaxf(m0, mx0);
        const float nm1 = fmaxf(m1, mx1);
        const float corr0 = __expf(m0 - nm0);
        const float corr1 = __expf(m1 - nm1);
        m0 = nm0; m1 = nm1;

        uint32_t ph0[8], ph1[8];            // P fragments (rows g, g+8)
        float sum0 = 0.f, sum1 = 0.f;
#pragma unroll
        for (int nt = 0; nt < 8; nt++) {
            const float p0 = __expf(sacc[nt][0] - nm0);
            const float p1 = __expf(sacc[nt][1] - nm0);
            const float p2 = __expf(sacc[nt][2] - nm1);
            const float p3 = __expf(sacc[nt][3] - nm1);
            sum0 += p0 + p1;
            sum1 += p2 + p3;
            ph0[nt] = pack_h2(p0, p1);
            ph1[nt] = pack_h2(p2, p3);
            oacc[nt][0] *= corr0; oacc[nt][1] *= corr0;
            oacc[nt][2] *= corr1; oacc[nt][3] *= corr1;
        }
        l0 = l0 * corr0 + sum0;
        l1 = l1 * corr1 + sum1;

        // ---- O += P V : P in registers, V via trans ldmatrix ----
#pragma unroll
        for (int kc = 0; kc < 4; kc++) {    // key chunks of 16
            uint32_t a[4] = {ph0[2 * kc], ph1[2 * kc],
                             ph0[2 * kc + 1], ph1[2 * kc + 1]};
#pragma unroll
            for (int ntD = 0; ntD < 8; ntD++) {
                uint32_t vf[2];
                ldm_x2t(vf[0], vf[1],
                        vsB + ((kc * 16 + mat2 * 8 + l8) * VSTRH + ntD * 8) * 2);
                mma_f16(oacc[ntD], a, vf);
            }
        }
    }

    // ---- finalize ----
    l0 += __shfl_xor_sync(0xffffffffu, l0, 1);
    l0 += __shfl_xor_sync(0xffffffffu, l0, 2);
    l1 += __shfl_xor_sync(0xffffffffu, l1, 1);
    l1 += __shfl_xor_sync(0xffffffffu, l1, 2);
    const float inv0 = 1.0f / l0;
    const float inv1 = 1.0f / l1;

    __half* y0 = &g_Y[((size_t)(b * Td + qrow0)) * Cd + h * HSd];
    __half* y1 = &g_Y[((size_t)(b * Td + qrow1)) * Cd + h * HSd];
#pragma unroll
    for (int nt = 0; nt < 8; nt++) {
        const int c = nt * 8 + 2 * tig;
        *(__half2*)&y0[c] = __floats2half2_rn(oacc[nt][0] * inv0,
                                              oacc[nt][1] * inv0);
        *(__half2*)&y1[c] = __floats2half2_rn(oacc[nt][2] * inv1,
                                              oacc[nt][3] * inv1);
    }
}

// ---------------- launch ----------------------------------------------------
extern "C" void kernel_launch(void* const* d_in, const int* in_sizes, int n_in,
                              void* d_out, int out_size)
{
    const float* x      = (const float*)d_in[0];
    const float* W_attn = (const float*)d_in[1];
    const float* b_attn = (const float*)d_in[2];
    const float* W_proj = (const float*)d_in[3];
    const float* b_proj = (const float*)d_in[4];
    float* out = (float*)d_out;

    (void)in_sizes; (void)n_in; (void)out_size;

    // one-time fp16 conversion of inputs/weights
    cvt_kernel<<<4096, 256>>>((const float4*)x,      Md * KDIM / 4,    0);
    cvt_kernel<<<4096, 256>>>((const float4*)W_attn, KDIM * N_QKV / 4, 1);
    cvt_kernel<<<2048, 256>>>((const float4*)W_proj, KDIM * Cd / 4,    2);

    dim3 gQKV(N_QKV / BN, Md / BM);       // (24, 64)
    gemm_f16_kernel<N_QKV, true><<<gQKV, 256>>>(b_attn, nullptr);

    dim3 gAtt(Td / 128, NHd, Bd);         // (16, 16, 4)
    attn_f16_kernel<<<gAtt, 256>>>();

    dim3 gProj(Cd / BN, Md / BM);         // (8, 64)
    gemm_f16_kernel<Cd, false><<<gProj, 256>>>(b_proj, out);
}

// round 13
// speedup vs baseline: 9.0215x; 1.2450x over previous
#include <cuda_runtime.h>
#include <cuda.h>
#include <cuda_fp16.h>
#include <math.h>
#include <stdint.h>

// Problem constants
#define Bd   4
#define Td   2048
#define Cd   1024
#define NHd  16
#define HSd  64
#define Md   (Bd * Td)          // 8192 rows
#define N_QKV (3 * Cd)          // 3072
#define KDIM Cd                 // 1024

// ---------------- scratch (device globals: allocation-free) ----------------
__device__ __align__(16) __half g_Q[Bd * NHd * Td * HSd];  // pre-scaled 0.125
__device__ __align__(16) __half g_K[Bd * NHd * Td * HSd];
__device__ __align__(16) __half g_V[Bd * NHd * Td * HSd];
__device__ __align__(16) __half g_Y[Md * Cd];              // attn out [B,T,C]
__device__ __align__(16) __half g_xh[Md * KDIM];           // fp16(x)       [M,K]
__device__ __align__(16) __half g_WAt[N_QKV * KDIM];       // fp16(W_attn^T)[N,K]
__device__ __align__(16) __half g_WPt[Cd * KDIM];          // fp16(W_proj^T)[N,K]
__device__ CUtensorMap d_tmaps[4];                         // X, WA, WP, Y

// ---------------- generic helpers -------------------------------------------
__device__ __forceinline__ uint32_t smem_u32(const void* p) {
    return (uint32_t)__cvta_generic_to_shared(p);
}
__device__ __forceinline__ uint32_t h2_bits(__half2 h) {
    return *reinterpret_cast<uint32_t*>(&h);
}
__device__ __forceinline__ uint32_t pack_h2(float a, float b) {
    return h2_bits(__floats2half2_rn(a, b));
}

__device__ __forceinline__ void ldm_x4(uint32_t r[4], uint32_t addr) {
    asm volatile("ldmatrix.sync.aligned.m8n8.x4.shared.b16 {%0,%1,%2,%3}, [%4];"
                 : "=r"(r[0]), "=r"(r[1]), "=r"(r[2]), "=r"(r[3]) : "r"(addr));
}
__device__ __forceinline__ void ldm_x2(uint32_t& r0, uint32_t& r1, uint32_t addr) {
    asm volatile("ldmatrix.sync.aligned.m8n8.x2.shared.b16 {%0,%1}, [%2];"
                 : "=r"(r0), "=r"(r1) : "r"(addr));
}
__device__ __forceinline__ void ldm_x2t(uint32_t& r0, uint32_t& r1, uint32_t addr) {
    asm volatile("ldmatrix.sync.aligned.m8n8.x2.trans.shared.b16 {%0,%1}, [%2];"
                 : "=r"(r0), "=r"(r1) : "r"(addr));
}
__device__ __forceinline__ void mma_f16(float c[4], const uint32_t a[4],
                                        const uint32_t b[2]) {
    asm volatile(
        "mma.sync.aligned.m16n8k16.row.col.f32.f16.f16.f32 "
        "{%0,%1,%2,%3}, {%4,%5,%6,%7}, {%8,%9}, {%0,%1,%2,%3};"
        : "+f"(c[0]), "+f"(c[1]), "+f"(c[2]), "+f"(c[3])
        : "r"(a[0]), "r"(a[1]), "r"(a[2]), "r"(a[3]), "r"(b[0]), "r"(b[1]));
}

__device__ __forceinline__ void cp16(uint32_t dst_smem, const void* src) {
    asm volatile("cp.async.cg.shared.global [%0], [%1], 16;\n"
                 :: "r"(dst_smem), "l"(src));
}
#define CP_COMMIT() asm volatile("cp.async.commit_group;\n" ::: "memory")
#define CP_WAIT2()  asm volatile("cp.async.wait_group 2;\n" ::: "memory")
#define CP_WAIT0()  asm volatile("cp.async.wait_group 0;\n" ::: "memory")

// ---------------- mbarrier / TMA (verbatim verified macro semantics) --------
#define MBARRIER_INIT(mbar_smem_addr, count) \
    asm volatile("mbarrier.init.shared.b64 [%0], %1;" \
                 :: "r"((uint32_t)(mbar_smem_addr)), "r"((uint32_t)(count)) \
                 : "memory")

#define MBARRIER_EXPECT_TX(mbar_smem_addr, tx_bytes) \
    asm volatile("mbarrier.arrive.expect_tx.shared.b64 _, [%0], %1;" \
                 :: "r"((uint32_t)(mbar_smem_addr)), "r"((uint32_t)(tx_bytes)) \
                 : "memory")

#define MBARRIER_WAIT_PARITY(mbar_smem_addr, phase_parity) do { \
    uint32_t _mbar = (uint32_t)(mbar_smem_addr); \
    uint32_t _parity = (uint32_t)(phase_parity); \
    uint32_t _done; \
    asm volatile( \
        "{\n\t" \
        ".reg .pred p;\n\t" \
        "mbarrier.try_wait.parity.acquire.cta.shared::cta.b64 p, [%1], %2;\n\t" \
        "selp.b32 %0, 1, 0, p;\n\t" \
        "}" \
        : "=r"(_done) : "r"(_mbar), "r"(_parity) : "memory"); \
    if (!_done) { \
        asm volatile( \
            "{\n\t" \
            ".reg .pred P1;\n\t" \
            "WAIT_LOOP_%=:\n\t" \
            "mbarrier.try_wait.parity.acquire.cta.shared::cta.b64 P1, [%0], %1, 0x989680;\n\t" \
            "@P1 bra.uni WAIT_DONE_%=;\n\t" \
            "bra.uni WAIT_LOOP_%=;\n\t" \
            "WAIT_DONE_%=:\n\t" \
            "}" \
            :: "r"(_mbar), "r"(_parity) : "memory"); \
    } \
} while(0)

__device__ __forceinline__ void tma2d(uint32_t dst, const CUtensorMap* m,
                                      int x, int y, uint32_t mbar) {
    asm volatile(
        "cp.async.bulk.tensor.2d.shared::cta.global.tile.mbarrier::complete_tx::bytes "
        "[%0], [%1, {%2, %3}], [%4];"
        :: "r"(dst), "l"(m), "r"(x), "r"(y), "r"(mbar) : "memory");
}

// ---------------- convert / transpose kernels (one-time) ---------------------
__global__ void cvt_x_kernel(const float4* __restrict__ src, int n4)
{
    uint2* dst = (uint2*)g_xh;
    for (int i = blockIdx.x * blockDim.x + threadIdx.x; i < n4;
         i += gridDim.x * blockDim.x) {
        float4 v = src[i];
        uint2 u;
        u.x = h2_bits(__floats2half2_rn(v.x, v.y));
        u.y = h2_bits(__floats2half2_rn(v.z, v.w));
        dst[i] = u;
    }
}

// src [R][C] fp32 -> dst [C][R] fp16
__global__ void transpose_cvt_kernel(const float* __restrict__ src,
                                     __half* __restrict__ dst, int R, int C)
{
    __shared__ float tile[32][33];
    const int bx = blockIdx.x * 32;
    const int by = blockIdx.y * 32;
    const int tx = threadIdx.x, ty = threadIdx.y;
#pragma unroll
    for (int j = 0; j < 32; j += 8)
        tile[ty + j][tx] = src[(size_t)(by + ty + j) * C + bx + tx];
    __syncthreads();
#pragma unroll
    for (int j = 0; j < 32; j += 8)
        dst[(size_t)(bx + ty + j) * R + by + tx] = __float2half(tile[tx][ty + j]);
}

// ---------------- FP16 GEMM: SW128-staged, dual producer (TMA / cp.async) ---
// 128x128 output tile per CTA, BK=64 halves (128B rows). A [M,K], B [N,K],
// both K-major, staged in SW128 layout (chunk c -> c ^ (row&7), 16B units).
// 3-stage pipeline. Consumer identical for both producer paths.

#define TC_STAGES 3
#define STAGE_BYTES 32768          // 16KB A + 16KB B
#define GNT (KDIM / 64)            // 16
#define TC_SMEM (TC_STAGES * STAGE_BYTES + 1024)

template <bool USE_TMA>
__device__ __forceinline__ void stage_copy_cp(uint32_t stA,
                                              const __half* Asrc,
                                              const __half* Bsrc,
                                              int rowBase, int colBase,
                                              int kt, int tid)
{
    if (USE_TMA) return;
#pragma unroll
    for (int i = 0; i < 4; i++) {
        const int id = tid + i * 256;          // chunk 0..1023
        const int row = id >> 3;
        const int col = id & 7;
        const uint32_t soff = row * 128 + ((col ^ (row & 7)) << 4);
        cp16(stA + soff,
             Asrc + (size_t)(rowBase + row) * KDIM + kt * 64 + col * 8);
        cp16(stA + 16384 + soff,
             Bsrc + (size_t)(colBase + row) * KDIM + kt * 64 + col * 8);
    }
    CP_COMMIT();
}

template <int NDIM, bool QKV, bool USE_TMA>
__global__ __launch_bounds__(256, 2)
void gemm_sw_kernel(const CUtensorMap* __restrict__ pA,
                    const CUtensorMap* __restrict__ pB,
                    const __half* __restrict__ Asrc,
                    const __half* __restrict__ Bsrc,
                    const float* __restrict__ bias,
                    float* __restrict__ out)
{
    extern __shared__ uint8_t smraw[];
    __shared__ __align__(8) uint64_t mbars[TC_STAGES];
    const uint32_t tiles = (smem_u32(smraw) + 1023u) & ~1023u;

    const int tid = threadIdx.x;
    const int lane = tid & 31;
    const int wid = tid >> 5;
    const int warpM = wid & 3;          // 4 warps x 32 rows
    const int warpN = wid >> 2;         // 2 warps x 64 cols
    const int g   = lane >> 2;
    const int tig = lane & 3;

    const int rowBase = blockIdx.y * 128;
    const int colBase = blockIdx.x * 128;

    if (USE_TMA) {
        if (tid == 0) {
#pragma unroll
            for (int s = 0; s < TC_STAGES; s++)
                MBARRIER_INIT(smem_u32(&mbars[s]), 1);
        }
        __syncthreads();
        if (tid == 0) {
#pragma unroll
            for (int s = 0; s < TC_STAGES; s++) {
                const uint32_t mb = smem_u32(&mbars[s]);
                MBARRIER_EXPECT_TX(mb, STAGE_BYTES);
                tma2d(tiles + s * STAGE_BYTES,         pA, s * 64, rowBase, mb);
                tma2d(tiles + s * STAGE_BYTES + 16384, pB, s * 64, colBase, mb);
            }
        }
    } else {
#pragma unroll
        for (int s = 0; s < TC_STAGES; s++)
            stage_copy_cp<USE_TMA>(tiles + s * STAGE_BYTES, Asrc, Bsrc,
                                   rowBase, colBase, s, tid);
    }

    // ldmatrix lane geometry (SW128: 16B chunk c -> c ^ (row&7))
    const int mat4 = lane >> 3;
    const int l8   = lane & 7;
    const int rA   = ((mat4 & 1) << 3) + l8;     // A row within 16
    const int aSel = mat4 >> 1;                  // A k16-half selector
    const int bRowOff = ((mat4 >> 1) << 3) + l8; // B row within 16-row pair
    const int bSel = mat4 & 1;                   // B k16-half selector
    const uint32_t aRowBase = warpM * 32 + rA;
    const uint32_t bRowBase = warpN * 64 + bRowOff;

    float acc[2][8][4];
#pragma unroll
    for (int mt = 0; mt < 2; mt++)
#pragma unroll
        for (int nt = 0; nt < 8; nt++)
#pragma unroll
            for (int i = 0; i < 4; i++) acc[mt][nt][i] = 0.f;

    for (int kt = 0; kt < GNT; kt++) {
        const int s = kt % TC_STAGES;
        if (USE_TMA) {
            MBARRIER_WAIT_PARITY(smem_u32(&mbars[s]), (uint32_t)(kt / TC_STAGES) & 1u);
        } else {
            if (kt >= GNT - TC_STAGES) { CP_WAIT0(); } else { CP_WAIT2(); }
            __syncthreads();
        }

        const uint32_t stA = tiles + s * STAGE_BYTES;
        const uint32_t stB = stA + 16384;

#pragma unroll
        for (int kc = 0; kc < 4; kc++) {
            uint32_t af[2][4];
#pragma unroll
            for (int mt = 0; mt < 2; mt++)
                ldm_x4(af[mt], stA + (aRowBase + mt * 16) * 128
                               + ((((kc << 1) + aSel) ^ l8) << 4));
            uint32_t bf[8][2];
#pragma unroll
            for (int ntp = 0; ntp < 4; ntp++) {
                uint32_t t4[4];
                ldm_x4(t4, stB + (bRowBase + ntp * 16) * 128
                           + ((((kc << 1) + bSel) ^ l8) << 4));
                bf[2 * ntp][0] = t4[0]; bf[2 * ntp][1] = t4[1];
                bf[2 * ntp + 1][0] = t4[2]; bf[2 * ntp + 1][1] = t4[3];
            }
#pragma unroll
            for (int mt = 0; mt < 2; mt++)
#pragma unroll
                for (int nt = 0; nt < 8; nt++)
                    mma_f16(acc[mt][nt], af[mt], bf[nt]);
        }
        __syncthreads();   // all warps done reading stage s

        if (kt + TC_STAGES < GNT) {
            if (USE_TMA) {
                if (tid == 0) {
                    const uint32_t mb = smem_u32(&mbars[s]);
                    MBARRIER_EXPECT_TX(mb, STAGE_BYTES);
                    tma2d(stA, pA, (kt + TC_STAGES) * 64, rowBase, mb);
                    tma2d(stB, pB, (kt + TC_STAGES) * 64, colBase, mb);
                }
            } else {
                stage_copy_cp<USE_TMA>(stA, Asrc, Bsrc, rowBase, colBase,
                                       kt + TC_STAGES, tid);
            }
        }
    }

    // ---------------- epilogue (R9-verified structure) ----------------
#pragma unroll
    for (int mt = 0; mt < 2; mt++) {
        const int r0 = rowBase + warpM * 32 + mt * 16 + g;
        const int r1 = r0 + 8;
#pragma unroll
        for (int nt = 0; nt < 8; nt++) {
            const int c = colBase + warpN * 64 + nt * 8 + 2 * tig;
            const float b0 = bias[c];
            const float b1 = bias[c + 1];
            if (QKV) {
                const int which = c / Cd;
                const int inner = c % Cd;
                const int h = inner / HSd;
                const int d = inner % HSd;
                const float sc = (which == 0) ? 0.125f : 1.0f;
                __half* dst = (which == 0) ? g_Q : (which == 1) ? g_K : g_V;
                {
                    const int bb = r0 / Td, t = r0 % Td;
                    const size_t idx = ((size_t)(bb * NHd + h) * Td + t) * HSd + d;
                    *(__half2*)&dst[idx] =
                        __floats2half2_rn((acc[mt][nt][0] + b0) * sc,
                                          (acc[mt][nt][1] + b1) * sc);
                }
                {
                    const int bb = r1 / Td, t = r1 % Td;
                    const size_t idx = ((size_t)(bb * NHd + h) * Td + t) * HSd + d;
                    *(__half2*)&dst[idx] =
                        __floats2half2_rn((acc[mt][nt][2] + b0) * sc,
                                          (acc[mt][nt][3] + b1) * sc);
                }
            } else {
                float2 v0, v1;
                v0.x = acc[mt][nt][0] + b0;
                v0.y = acc[mt][nt][1] + b1;
                v1.x = acc[mt][nt][2] + b0;
                v1.y = acc[mt][nt][3] + b1;
                *(float2*)&out[(size_t)r0 * NDIM + c] = v0;
                *(float2*)&out[(size_t)r1 * NDIM + c] = v1;
            }
        }
    }
}

// ---------------- FP16 tensor-core flash attention (unchanged, passing) ------
#define QSTRH 72
#define KSTRH 72
#define VSTRH 72

__global__ __launch_bounds__(256, 2)
void attn_f16_kernel()
{
    __shared__ __half Qs[128 * QSTRH];
    __shared__ __half Ks[64 * KSTRH];
    __shared__ __half Vs[64 * VSTRH];

    const int b = blockIdx.z;
    const int h = blockIdx.y;
    const int qbase = blockIdx.x * 128;

    const int tid  = threadIdx.x;
    const int lane = tid & 31;
    const int w    = tid >> 5;
    const int g    = lane >> 2;
    const int tig  = lane & 3;

    const uint32_t qsB = smem_u32(Qs);
    const uint32_t ksB = smem_u32(Ks);
    const uint32_t vsB = smem_u32(Vs);

    const size_t headOff = (size_t)(b * NHd + h) * Td * HSd;
    const __half* Kg = &g_K[headOff];
    const __half* Vg = &g_V[headOff];
    const __half* Qg = &g_Q[headOff + (size_t)qbase * HSd];

#pragma unroll
    for (int j = 0; j < 4; j++) {
        const int f = tid + j * 256;
        const int r = f >> 3;
        const int c8 = (f & 7) << 3;
        *(uint4*)&Qs[r * QSTRH + c8] = *(const uint4*)&Qg[r * HSd + c8];
    }
    __syncthreads();

    const int mat4 = lane >> 3;
    const int rQ   = w * 16 + ((mat4 & 1) << 3) + (lane & 7);
    const int cQ   = (mat4 >> 1) << 3;
    const int l8   = lane & 7;
    const int mat2 = (lane & 15) >> 3;

    uint32_t qf[4][4];
#pragma unroll
    for (int kc = 0; kc < 4; kc++)
        ldm_x4(qf[kc], qsB + (rQ * QSTRH + kc * 16 + cQ) * 2);

    const int qrow0 = qbase + w * 16 + g;
    const int qrow1 = qrow0 + 8;

    float oacc[8][4];
#pragma unroll
    for (int nt = 0; nt < 8; nt++)
#pragma unroll
        for (int e = 0; e < 4; e++) oacc[nt][e] = 0.f;
    float m0 = -1e30f, m1 = -1e30f, l0 = 0.f, l1 = 0.f;

    const int ntiles = 2 * blockIdx.x + 2;

    for (int t = 0; t < ntiles; t++) {
        __syncthreads();

        const __half* Kt = Kg + t * 64 * HSd;
        const __half* Vt = Vg + t * 64 * HSd;
#pragma unroll
        for (int j = 0; j < 2; j++) {
            const int f = tid + j * 256;
            const int r = f >> 3;
            const int c8 = (f & 7) << 3;
            *(uint4*)&Ks[r * KSTRH + c8] = *(const uint4*)&Kt[r * HSd + c8];
            *(uint4*)&Vs[r * VSTRH + c8] = *(const uint4*)&Vt[r * HSd + c8];
        }
        __syncthreads();

        float sacc[8][4];
#pragma unroll
        for (int nt = 0; nt < 8; nt++)
#pragma unroll
            for (int e = 0; e < 4; e++) sacc[nt][e] = 0.f;

#pragma unroll
        for (int kc = 0; kc < 4; kc++) {
#pragma unroll
            for (int nt = 0; nt < 8; nt++) {
                uint32_t kf0, kf1;
                ldm_x2(kf0, kf1,
                       ksB + ((nt * 8 + l8) * KSTRH + kc * 16 + mat2 * 8) * 2);
                uint32_t bf[2] = {kf0, kf1};
                mma_f16(sacc[nt], qf[kc], bf);
            }
        }

        if (t >= 2 * (int)blockIdx.x) {
            const int colb = t * 64;
#pragma unroll
            for (int nt = 0; nt < 8; nt++) {
                const int c0 = colb + nt * 8 + 2 * tig;
                if (c0     > qrow0) sacc[nt][0] = -1e30f;
                if (c0 + 1 > qrow0) sacc[nt][1] = -1e30f;
                if (c0     > qrow1) sacc[nt][2] = -1e30f;
                if (c0 + 1 > qrow1) sacc[nt][3] = -1e30f;
            }
        }

        float mx0 = -1e30f, mx1 = -1e30f;
#pragma unroll
        for (int nt = 0; nt < 8; nt++) {
            mx0 = fmaxf(mx0, fmaxf(sacc[nt][0], sacc[nt][1]));
            mx1 = fmaxf(mx1, fmaxf(sacc[nt][2], sacc[nt][3]));
        }
        mx0 = fmaxf(mx0, __shfl_xor_sync(0xffffffffu, mx0, 1));
        mx0 = fmaxf(mx0, __shfl_xor_sync(0xffffffffu, mx0, 2));
        mx1 = fmaxf(mx1, __shfl_xor_sync(0xffffffffu, mx1, 1));
        mx1 = fmaxf(mx1, __shfl_xor_sync(0xffffffffu, mx1, 2));

        const float nm0 = fmaxf(m0, mx0);
        const float nm1 = fmaxf(m1, mx1);
        const float corr0 = __expf(m0 - nm0);
        const float corr1 = __expf(m1 - nm1);
        m0 = nm0; m1 = nm1;

        uint32_t ph0[8], ph1[8];
        float sum0 = 0.f, sum1 = 0.f;
#pragma unroll
        for (int nt = 0; nt < 8; nt++) {
            const float p0 = __expf(sacc[nt][0] - nm0);
            const float p1 = __expf(sacc[nt][1] - nm0);
            const float p2 = __expf(sacc[nt][2] - nm1);
            const float p3 = __expf(sacc[nt][3] - nm1);
            sum0 += p0 + p1;
            sum1 += p2 + p3;
            ph0[nt] = pack_h2(p0, p1);
            ph1[nt] = pack_h2(p2, p3);
            oacc[nt][0] *= corr0; oacc[nt][1] *= corr0;
            oacc[nt][2] *= corr1; oacc[nt][3] *= corr1;
        }
        l0 = l0 * corr0 + sum0;
        l1 = l1 * corr1 + sum1;

#pragma unroll
        for (int kc = 0; kc < 4; kc++) {
            uint32_t a[4] = {ph0[2 * kc], ph1[2 * kc],
                             ph0[2 * kc + 1], ph1[2 * kc + 1]};
#pragma unroll
            for (int ntD = 0; ntD < 8; ntD++) {
                uint32_t vf[2];
                ldm_x2t(vf[0], vf[1],
                        vsB + ((kc * 16 + mat2 * 8 + l8) * VSTRH + ntD * 8) * 2);
                mma_f16(oacc[ntD], a, vf);
            }
        }
    }

    l0 += __shfl_xor_sync(0xffffffffu, l0, 1);
    l0 += __shfl_xor_sync(0xffffffffu, l0, 2);
    l1 += __shfl_xor_sync(0xffffffffu, l1, 1);
    l1 += __shfl_xor_sync(0xffffffffu, l1, 2);
    const float inv0 = 1.0f / l0;
    const float inv1 = 1.0f / l1;

    __half* y0 = &g_Y[((size_t)(b * Td + qrow0)) * Cd + h * HSd];
    __half* y1 = &g_Y[((size_t)(b * Td + qrow1)) * Cd + h * HSd];
#pragma unroll
    for (int nt = 0; nt < 8; nt++) {
        const int c = nt * 8 + 2 * tig;
        *(__half2*)&y0[c] = __floats2half2_rn(oacc[nt][0] * inv0,
                                              oacc[nt][1] * inv0);
        *(__half2*)&y1[c] = __floats2half2_rn(oacc[nt][2] * inv1,
                                              oacc[nt][3] * inv1);
    }
}

// ---------------- host launch ------------------------------------------------
typedef CUresult (*PFN_tmEncode)(
    CUtensorMap*, CUtensorMapDataType, cuuint32_t, void*,
    const cuuint64_t*, const cuuint64_t*, const cuuint32_t*, const cuuint32_t*,
    CUtensorMapInterleave, CUtensorMapSwizzle, CUtensorMapL2promotion,
    CUtensorMapFloatOOBfill);

static bool make_map(PFN_tmEncode enc, CUtensorMap* tm, void* base, uint64_t rows)
{
    cuuint64_t dims[2]    = {(cuuint64_t)KDIM, (cuuint64_t)rows};
    cuuint64_t strides[1] = {(cuuint64_t)KDIM * 2};
    cuuint32_t box[2]     = {64, 128};
    cuuint32_t es[2]      = {1, 1};
    CUresult r = enc(tm, CU_TENSOR_MAP_DATA_TYPE_FLOAT16, 2, base, dims, strides,
                     box, es, CU_TENSOR_MAP_INTERLEAVE_NONE,
                     CU_TENSOR_MAP_SWIZZLE_128B,
                     CU_TENSOR_MAP_L2_PROMOTION_L2_128B,
                     CU_TENSOR_MAP_FLOAT_OOB_FILL_NONE);
    return r == CUDA_SUCCESS;
}

extern "C" void kernel_launch(void* const* d_in, const int* in_sizes, int n_in,
                              void* d_out, int out_size)
{
    const float* x      = (const float*)d_in[0];
    const float* W_attn = (const float*)d_in[1];
    const float* b_attn = (const float*)d_in[2];
    const float* W_proj = (const float*)d_in[3];
    const float* b_proj = (const float*)d_in[4];
    float* out = (float*)d_out;

    (void)in_sizes; (void)n_in; (void)out_size;

    // real device addresses (NEVER pass __device__ symbols from host directly)
    void *p_xh, *p_wat, *p_wpt, *p_y;
    cudaGetSymbolAddress(&p_xh,  g_xh);
    cudaGetSymbolAddress(&p_wat, g_WAt);
    cudaGetSymbolAddress(&p_wpt, g_WPt);
    cudaGetSymbolAddress(&p_y,   g_Y);

    // try to build tensormaps; fall back to cp.async path on ANY failure
    static CUtensorMap h_maps[4];        // static: survives for graph replays
    bool use_tma = false;
    {
        void* fn = nullptr;
        cudaDriverEntryPointQueryResult qs =
            cudaDriverEntryPointSymbolNotFound;
        cudaError_t e = cudaGetDriverEntryPoint("cuTensorMapEncodeTiled", &fn,
                                                cudaEnableDefault, &qs);
        if (e == cudaSuccess && fn && qs == cudaDriverEntryPointSuccess) {
            PFN_tmEncode enc = (PFN_tmEncode)fn;
            bool ok = make_map(enc, &h_maps[0], p_xh,  Md)
                   && make_map(enc, &h_maps[1], p_wat, N_QKV)
                   && make_map(enc, &h_maps[2], p_wpt, Cd)
                   && make_map(enc, &h_maps[3], p_y,   Md);
            if (ok) {
                cudaMemcpyToSymbolAsync(d_tmaps, h_maps, sizeof(h_maps), 0,
                                        cudaMemcpyHostToDevice, 0);
                use_tma = true;
            }
        }
    }
    void* p_maps = nullptr;
    cudaGetSymbolAddress(&p_maps, d_tmaps);
    CUtensorMap* maps = (CUtensorMap*)p_maps;

    cudaFuncSetAttribute(gemm_sw_kernel<N_QKV, true, true>,
                         cudaFuncAttributeMaxDynamicSharedMemorySize, TC_SMEM);
    cudaFuncSetAttribute(gemm_sw_kernel<N_QKV, true, false>,
                         cudaFuncAttributeMaxDynamicSharedMemorySize, TC_SMEM);
    cudaFuncSetAttribute(gemm_sw_kernel<Cd, false, true>,
                         cudaFuncAttributeMaxDynamicSharedMemorySize, TC_SMEM);
    cudaFuncSetAttribute(gemm_sw_kernel<Cd, false, false>,
                         cudaFuncAttributeMaxDynamicSharedMemorySize, TC_SMEM);

    // one-time fp16 conversion / weight transposes
    cvt_x_kernel<<<4096, 256>>>((const float4*)x, Md * KDIM / 4);
    transpose_cvt_kernel<<<dim3(N_QKV / 32, KDIM / 32), dim3(32, 8)>>>(
        W_attn, (__half*)p_wat, KDIM, N_QKV);
    transpose_cvt_kernel<<<dim3(Cd / 32, KDIM / 32), dim3(32, 8)>>>(
        W_proj, (__half*)p_wpt, KDIM, Cd);

    dim3 gQKV(N_QKV / 128, Md / 128);     // (24, 64)
    dim3 gProj(Cd / 128, Md / 128);       // (8, 64)
    dim3 gAtt(Td / 128, NHd, Bd);         // (16, 16, 4)

    if (use_tma) {
        gemm_sw_kernel<N_QKV, true, true><<<gQKV, 256, TC_SMEM>>>(
            maps + 0, maps + 1, (const __half*)p_xh, (const __half*)p_wat,
            b_attn, nullptr);
        attn_f16_kernel<<<gAtt, 256>>>();
        gemm_sw_kernel<Cd, false, true><<<gProj, 256, TC_SMEM>>>(
            maps + 3, maps + 2, (const __half*)p_y, (const __half*)p_wpt,
            b_proj, out);
    } else {
        gemm_sw_kernel<N_QKV, true, false><<<gQKV, 256, TC_SMEM>>>(
            nullptr, nullptr, (const __half*)p_xh, (const __half*)p_wat,
            b_attn, nullptr);
        attn_f16_kernel<<<gAtt, 256>>>();
        gemm_sw_kernel<Cd, false, false><<<gProj, 256, TC_SMEM>>>(
            nullptr, nullptr, (const __half*)p_y, (const __half*)p_wpt,
            b_proj, out);
    }
}

// round 14
// speedup vs baseline: 9.7636x; 1.0823x over previous
#include <cuda_runtime.h>
#include <cuda.h>
#include <cuda_fp16.h>
#include <math.h>
#include <stdint.h>

// Problem constants
#define Bd   4
#define Td   2048
#define Cd   1024
#define NHd  16
#define HSd  64
#define Md   (Bd * Td)          // 8192 rows
#define N_QKV (3 * Cd)          // 3072
#define KDIM Cd                 // 1024

// ---------------- scratch (device globals: allocation-free) ----------------
__device__ __align__(16) __half g_Q[Bd * NHd * Td * HSd];  // pre-scaled 0.125
__device__ __align__(16) __half g_K[Bd * NHd * Td * HSd];
__device__ __align__(16) __half g_V[Bd * NHd * Td * HSd];
__device__ __align__(16) __half g_Y[Md * Cd];              // attn out [B,T,C]
__device__ __align__(16) __half g_xh[Md * KDIM];           // fp16(x)       [M,K]
__device__ __align__(16) __half g_WAt[N_QKV * KDIM];       // fp16(W_attn^T)[N,K]
__device__ __align__(16) __half g_WPt[Cd * KDIM];          // fp16(W_proj^T)[N,K]
__device__ CUtensorMap d_tmaps[4];                         // X, WA, WP, Y

// ---------------- generic helpers -------------------------------------------
__device__ __forceinline__ uint32_t smem_u32(const void* p) {
    return (uint32_t)__cvta_generic_to_shared(p);
}
__device__ __forceinline__ uint32_t h2_bits(__half2 h) {
    return *reinterpret_cast<uint32_t*>(&h);
}
__device__ __forceinline__ uint32_t pack_h2(float a, float b) {
    return h2_bits(__floats2half2_rn(a, b));
}

__device__ __forceinline__ void ldm_x4(uint32_t r[4], uint32_t addr) {
    asm volatile("ldmatrix.sync.aligned.m8n8.x4.shared.b16 {%0,%1,%2,%3}, [%4];"
                 : "=r"(r[0]), "=r"(r[1]), "=r"(r[2]), "=r"(r[3]) : "r"(addr));
}
__device__ __forceinline__ void ldm_x4t(uint32_t r[4], uint32_t addr) {
    asm volatile("ldmatrix.sync.aligned.m8n8.x4.trans.shared.b16 {%0,%1,%2,%3}, [%4];"
                 : "=r"(r[0]), "=r"(r[1]), "=r"(r[2]), "=r"(r[3]) : "r"(addr));
}
__device__ __forceinline__ void mma_f16(float c[4], const uint32_t a[4],
                                        const uint32_t b[2]) {
    asm volatile(
        "mma.sync.aligned.m16n8k16.row.col.f32.f16.f16.f32 "
        "{%0,%1,%2,%3}, {%4,%5,%6,%7}, {%8,%9}, {%0,%1,%2,%3};"
        : "+f"(c[0]), "+f"(c[1]), "+f"(c[2]), "+f"(c[3])
        : "r"(a[0]), "r"(a[1]), "r"(a[2]), "r"(a[3]), "r"(b[0]), "r"(b[1]));
}

__device__ __forceinline__ void cp16(uint32_t dst_smem, const void* src) {
    asm volatile("cp.async.cg.shared.global [%0], [%1], 16;\n"
                 :: "r"(dst_smem), "l"(src));
}
#define CP_COMMIT() asm volatile("cp.async.commit_group;\n" ::: "memory")
#define CP_WAIT2()  asm volatile("cp.async.wait_group 2;\n" ::: "memory")
#define CP_WAIT1()  asm volatile("cp.async.wait_group 1;\n" ::: "memory")
#define CP_WAIT0()  asm volatile("cp.async.wait_group 0;\n" ::: "memory")

// ---------------- mbarrier / TMA (verified macro semantics) ------------------
#define MBARRIER_INIT(mbar_smem_addr, count) \
    asm volatile("mbarrier.init.shared.b64 [%0], %1;" \
                 :: "r"((uint32_t)(mbar_smem_addr)), "r"((uint32_t)(count)) \
                 : "memory")

#define MBARRIER_EXPECT_TX(mbar_smem_addr, tx_bytes) \
    asm volatile("mbarrier.arrive.expect_tx.shared.b64 _, [%0], %1;" \
                 :: "r"((uint32_t)(mbar_smem_addr)), "r"((uint32_t)(tx_bytes)) \
                 : "memory")

#define MBARRIER_WAIT_PARITY(mbar_smem_addr, phase_parity) do { \
    uint32_t _mbar = (uint32_t)(mbar_smem_addr); \
    uint32_t _parity = (uint32_t)(phase_parity); \
    uint32_t _done; \
    asm volatile( \
        "{\n\t" \
        ".reg .pred p;\n\t" \
        "mbarrier.try_wait.parity.acquire.cta.shared::cta.b64 p, [%1], %2;\n\t" \
        "selp.b32 %0, 1, 0, p;\n\t" \
        "}" \
        : "=r"(_done) : "r"(_mbar), "r"(_parity) : "memory"); \
    if (!_done) { \
        asm volatile( \
            "{\n\t" \
            ".reg .pred P1;\n\t" \
            "WAIT_LOOP_%=:\n\t" \
            "mbarrier.try_wait.parity.acquire.cta.shared::cta.b64 P1, [%0], %1, 0x989680;\n\t" \
            "@P1 bra.uni WAIT_DONE_%=;\n\t" \
            "bra.uni WAIT_LOOP_%=;\n\t" \
            "WAIT_DONE_%=:\n\t" \
            "}" \
            :: "r"(_mbar), "r"(_parity) : "memory"); \
    } \
} while(0)

__device__ __forceinline__ void tma2d(uint32_t dst, const CUtensorMap* m,
                                      int x, int y, uint32_t mbar) {
    asm volatile(
        "cp.async.bulk.tensor.2d.shared::cta.global.tile.mbarrier::complete_tx::bytes "
        "[%0], [%1, {%2, %3}], [%4];"
        :: "r"(dst), "l"(m), "r"(x), "r"(y), "r"(mbar) : "memory");
}

// ---------------- convert / transpose kernels (one-time) ---------------------
__global__ void cvt_x_kernel(const float4* __restrict__ src, int n4)
{
    uint2* dst = (uint2*)g_xh;
    for (int i = blockIdx.x * blockDim.x + threadIdx.x; i < n4;
         i += gridDim.x * blockDim.x) {
        float4 v = src[i];
        uint2 u;
        u.x = h2_bits(__floats2half2_rn(v.x, v.y));
        u.y = h2_bits(__floats2half2_rn(v.z, v.w));
        dst[i] = u;
    }
}

// src [R][C] fp32 -> dst [C][R] fp16
__global__ void transpose_cvt_kernel(const float* __restrict__ src,
                                     __half* __restrict__ dst, int R, int C)
{
    __shared__ float tile[32][33];
    const int bx = blockIdx.x * 32;
    const int by = blockIdx.y * 32;
    const int tx = threadIdx.x, ty = threadIdx.y;
#pragma unroll
    for (int j = 0; j < 32; j += 8)
        tile[ty + j][tx] = src[(size_t)(by + ty + j) * C + bx + tx];
    __syncthreads();
#pragma unroll
    for (int j = 0; j < 32; j += 8)
        dst[(size_t)(bx + ty + j) * R + by + tx] = __float2half(tile[tx][ty + j]);
}

// ---------------- FP16 GEMM (unchanged from R12, passing) --------------------
#define TC_STAGES 3
#define STAGE_BYTES 32768
#define GNT (KDIM / 64)
#define TC_SMEM (TC_STAGES * STAGE_BYTES + 1024)

template <bool USE_TMA>
__device__ __forceinline__ void stage_copy_cp(uint32_t stA,
                                              const __half* Asrc,
                                              const __half* Bsrc,
                                              int rowBase, int colBase,
                                              int kt, int tid)
{
    if (USE_TMA) return;
#pragma unroll
    for (int i = 0; i < 4; i++) {
        const int id = tid + i * 256;
        const int row = id >> 3;
        const int col = id & 7;
        const uint32_t soff = row * 128 + ((col ^ (row & 7)) << 4);
        cp16(stA + soff,
             Asrc + (size_t)(rowBase + row) * KDIM + kt * 64 + col * 8);
        cp16(stA + 16384 + soff,
             Bsrc + (size_t)(colBase + row) * KDIM + kt * 64 + col * 8);
    }
    CP_COMMIT();
}

template <int NDIM, bool QKV, bool USE_TMA>
__global__ __launch_bounds__(256, 2)
void gemm_sw_kernel(const CUtensorMap* __restrict__ pA,
                    const CUtensorMap* __restrict__ pB,
                    const __half* __restrict__ Asrc,
                    const __half* __restrict__ Bsrc,
                    const float* __restrict__ bias,
                    float* __restrict__ out)
{
    extern __shared__ uint8_t smraw[];
    __shared__ __align__(8) uint64_t mbars[TC_STAGES];
    const uint32_t tiles = (smem_u32(smraw) + 1023u) & ~1023u;

    const int tid = threadIdx.x;
    const int lane = tid & 31;
    const int wid = tid >> 5;
    const int warpM = wid & 3;
    const int warpN = wid >> 2;
    const int g   = lane >> 2;
    const int tig = lane & 3;

    const int rowBase = blockIdx.y * 128;
    const int colBase = blockIdx.x * 128;

    if (USE_TMA) {
        if (tid == 0) {
#pragma unroll
            for (int s = 0; s < TC_STAGES; s++)
                MBARRIER_INIT(smem_u32(&mbars[s]), 1);
        }
        __syncthreads();
        if (tid == 0) {
#pragma unroll
            for (int s = 0; s < TC_STAGES; s++) {
                const uint32_t mb = smem_u32(&mbars[s]);
                MBARRIER_EXPECT_TX(mb, STAGE_BYTES);
                tma2d(tiles + s * STAGE_BYTES,         pA, s * 64, rowBase, mb);
                tma2d(tiles + s * STAGE_BYTES + 16384, pB, s * 64, colBase, mb);
            }
        }
    } else {
#pragma unroll
        for (int s = 0; s < TC_STAGES; s++)
            stage_copy_cp<USE_TMA>(tiles + s * STAGE_BYTES, Asrc, Bsrc,
                                   rowBase, colBase, s, tid);
    }

    const int mat4 = lane >> 3;
    const int l8   = lane & 7;
    const int rA   = ((mat4 & 1) << 3) + l8;
    const int aSel = mat4 >> 1;
    const int bRowOff = ((mat4 >> 1) << 3) + l8;
    const int bSel = mat4 & 1;
    const uint32_t aRowBase = warpM * 32 + rA;
    const uint32_t bRowBase = warpN * 64 + bRowOff;

    float acc[2][8][4];
#pragma unroll
    for (int mt = 0; mt < 2; mt++)
#pragma unroll
        for (int nt = 0; nt < 8; nt++)
#pragma unroll
            for (int i = 0; i < 4; i++) acc[mt][nt][i] = 0.f;

    for (int kt = 0; kt < GNT; kt++) {
        const int s = kt % TC_STAGES;
        if (USE_TMA) {
            MBARRIER_WAIT_PARITY(smem_u32(&mbars[s]), (uint32_t)(kt / TC_STAGES) & 1u);
        } else {
            if (kt >= GNT - TC_STAGES) { CP_WAIT0(); } else { CP_WAIT2(); }
            __syncthreads();
        }

        const uint32_t stA = tiles + s * STAGE_BYTES;
        const uint32_t stB = stA + 16384;

#pragma unroll
        for (int kc = 0; kc < 4; kc++) {
            uint32_t af[2][4];
#pragma unroll
            for (int mt = 0; mt < 2; mt++)
                ldm_x4(af[mt], stA + (aRowBase + mt * 16) * 128
                               + ((((kc << 1) + aSel) ^ l8) << 4));
            uint32_t bf[8][2];
#pragma unroll
            for (int ntp = 0; ntp < 4; ntp++) {
                uint32_t t4[4];
                ldm_x4(t4, stB + (bRowBase + ntp * 16) * 128
                           + ((((kc << 1) + bSel) ^ l8) << 4));
                bf[2 * ntp][0] = t4[0]; bf[2 * ntp][1] = t4[1];
                bf[2 * ntp + 1][0] = t4[2]; bf[2 * ntp + 1][1] = t4[3];
            }
#pragma unroll
            for (int mt = 0; mt < 2; mt++)
#pragma unroll
                for (int nt = 0; nt < 8; nt++)
                    mma_f16(acc[mt][nt], af[mt], bf[nt]);
        }
        __syncthreads();

        if (kt + TC_STAGES < GNT) {
            if (USE_TMA) {
                if (tid == 0) {
                    const uint32_t mb = smem_u32(&mbars[s]);
                    MBARRIER_EXPECT_TX(mb, STAGE_BYTES);
                    tma2d(stA, pA, (kt + TC_STAGES) * 64, rowBase, mb);
                    tma2d(stB, pB, (kt + TC_STAGES) * 64, colBase, mb);
                }
            } else {
                stage_copy_cp<USE_TMA>(stA, Asrc, Bsrc, rowBase, colBase,
                                       kt + TC_STAGES, tid);
            }
        }
    }

#pragma unroll
    for (int mt = 0; mt < 2; mt++) {
        const int r0 = rowBase + warpM * 32 + mt * 16 + g;
        const int r1 = r0 + 8;
#pragma unroll
        for (int nt = 0; nt < 8; nt++) {
            const int c = colBase + warpN * 64 + nt * 8 + 2 * tig;
            const float b0 = bias[c];
            const float b1 = bias[c + 1];
            if (QKV) {
                const int which = c / Cd;
                const int inner = c % Cd;
                const int h = inner / HSd;
                const int d = inner % HSd;
                const float sc = (which == 0) ? 0.125f : 1.0f;
                __half* dst = (which == 0) ? g_Q : (which == 1) ? g_K : g_V;
                {
                    const int bb = r0 / Td, t = r0 % Td;
                    const size_t idx = ((size_t)(bb * NHd + h) * Td + t) * HSd + d;
                    *(__half2*)&dst[idx] =
                        __floats2half2_rn((acc[mt][nt][0] + b0) * sc,
                                          (acc[mt][nt][1] + b1) * sc);
                }
                {
                    const int bb = r1 / Td, t = r1 % Td;
                    const size_t idx = ((size_t)(bb * NHd + h) * Td + t) * HSd + d;
                    *(__half2*)&dst[idx] =
                        __floats2half2_rn((acc[mt][nt][2] + b0) * sc,
                                          (acc[mt][nt][3] + b1) * sc);
                }
            } else {
                float2 v0, v1;
                v0.x = acc[mt][nt][0] + b0;
                v0.y = acc[mt][nt][1] + b1;
                v1.x = acc[mt][nt][2] + b0;
                v1.y = acc[mt][nt][3] + b1;
                *(float2*)&out[(size_t)r0 * NDIM + c] = v0;
                *(float2*)&out[(size_t)r1 * NDIM + c] = v1;
            }
        }
    }
}

// ---------------- FP16 flash attention v2 ------------------------------------
// Double-buffered cp.async K/V staging, x4 ldmatrix, reversed block order.
// Dynamic SMEM: Q 18432B | K 2x9216B | V 2x9216B = 55296B.

#define QSTR 72                     // halves (144B row)
#define ATT_Q_OFF 0
#define ATT_K_OFF 18432
#define ATT_V_OFF 36864
#define ATT_STG   9216
#define ATT_SMEM  (55296 + 256)

__device__ __forceinline__ void attn_stage_kv(uint32_t ksS, uint32_t vsS,
                                              const __half* Kt,
                                              const __half* Vt, int tid)
{
#pragma unroll
    for (int i = 0; i < 2; i++) {
        const int id = tid + i * 256;       // chunk 0..511
        const int row = id >> 3;
        const int col = id & 7;
        cp16(ksS + row * 144 + col * 16, Kt + row * HSd + col * 8);
        cp16(vsS + row * 144 + col * 16, Vt + row * HSd + col * 8);
    }
    CP_COMMIT();
}

__global__ __launch_bounds__(256, 2)
void attn_f16_kernel()
{
    extern __shared__ uint8_t smraw[];
    const uint32_t base = (smem_u32(smraw) + 255u) & ~255u;
    const uint32_t qsB = base + ATT_Q_OFF;

    const int b = blockIdx.z;
    const int h = blockIdx.y;
    const int bx = gridDim.x - 1 - blockIdx.x;   // longest CTAs first
    const int qbase = bx * 128;

    const int tid  = threadIdx.x;
    const int lane = tid & 31;
    const int w    = tid >> 5;
    const int g    = lane >> 2;
    const int tig  = lane & 3;
    const int l8   = lane & 7;
    const int mat2 = (lane & 15) >> 3;
    const int hi   = lane >> 4;

    const size_t headOff = (size_t)(b * NHd + h) * Td * HSd;
    const __half* Kg = &g_K[headOff];
    const __half* Vg = &g_V[headOff];
    const __half* Qg = &g_Q[headOff + (size_t)qbase * HSd];

    const int ntiles = 2 * bx + 2;

    // prefetch tile 0 into stage 0
    attn_stage_kv(base + ATT_K_OFF, base + ATT_V_OFF, Kg, Vg, tid);

    // stage Q (128 x 64 halves)
#pragma unroll
    for (int j = 0; j < 4; j++) {
        const int f = tid + j * 256;
        const int r = f >> 3;
        const int c8 = (f & 7) << 3;
        *(uint4*)(smraw + (qsB - smem_u32(smraw)) + r * 144 + c8 * 2) =
            *(const uint4*)&Qg[r * HSd + c8];
    }
    __syncthreads();

    // Q fragments
    const int mat4 = lane >> 3;
    const int rQ   = w * 16 + ((mat4 & 1) << 3) + l8;
    const int cQ   = (mat4 >> 1) << 3;
    uint32_t qf[4][4];
#pragma unroll
    for (int kc = 0; kc < 4; kc++)
        ldm_x4(qf[kc], qsB + rQ * 144 + (kc * 16 + cQ) * 2);

    const int qrow0 = qbase + w * 16 + g;
    const int qrow1 = qrow0 + 8;

    float oacc[8][4];
#pragma unroll
    for (int nt = 0; nt < 8; nt++)
#pragma unroll
        for (int e = 0; e < 4; e++) oacc[nt][e] = 0.f;
    float m0 = -1e30f, m1 = -1e30f, l0 = 0.f, l1 = 0.f;

    for (int t = 0; t < ntiles; t++) {
        const uint32_t ksS = base + ATT_K_OFF + (t & 1) * ATT_STG;
        const uint32_t vsS = base + ATT_V_OFF + (t & 1) * ATT_STG;

        if (t + 1 < ntiles) {
            attn_stage_kv(base + ATT_K_OFF + ((t + 1) & 1) * ATT_STG,
                          base + ATT_V_OFF + ((t + 1) & 1) * ATT_STG,
                          Kg + (t + 1) * 64 * HSd, Vg + (t + 1) * 64 * HSd, tid);
            CP_WAIT1();
        } else {
            CP_WAIT0();
        }
        __syncthreads();

        // ---- S = Q K^T ----
        float sacc[8][4];
#pragma unroll
        for (int nt = 0; nt < 8; nt++)
#pragma unroll
            for (int e = 0; e < 4; e++) sacc[nt][e] = 0.f;

#pragma unroll
        for (int kc = 0; kc < 4; kc++) {
#pragma unroll
            for (int ntp = 0; ntp < 4; ntp++) {
                uint32_t t4[4];
                ldm_x4(t4, ksS + (ntp * 16 + hi * 8 + l8) * 144
                           + (kc * 16 + mat2 * 8) * 2);
                uint32_t b0[2] = {t4[0], t4[1]};
                uint32_t b1[2] = {t4[2], t4[3]};
                mma_f16(sacc[2 * ntp], qf[kc], b0);
                mma_f16(sacc[2 * ntp + 1], qf[kc], b1);
            }
        }

        // ---- causal mask ----
        if (t >= 2 * bx) {
            const int colb = t * 64;
#pragma unroll
            for (int nt = 0; nt < 8; nt++) {
                const int c0 = colb + nt * 8 + 2 * tig;
                if (c0     > qrow0) sacc[nt][0] = -1e30f;
                if (c0 + 1 > qrow0) sacc[nt][1] = -1e30f;
                if (c0     > qrow1) sacc[nt][2] = -1e30f;
                if (c0 + 1 > qrow1) sacc[nt][3] = -1e30f;
            }
        }

        // ---- online softmax ----
        float mx0 = -1e30f, mx1 = -1e30f;
#pragma unroll
        for (int nt = 0; nt < 8; nt++) {
            mx0 = fmaxf(mx0, fmaxf(sacc[nt][0], sacc[nt][1]));
            mx1 = fmaxf(mx1, fmaxf(sacc[nt][2], sacc[nt][3]));
        }
        mx0 = fmaxf(mx0, __shfl_xor_sync(0xffffffffu, mx0, 1));
        mx0 = fmaxf(mx0, __shfl_xor_sync(0xffffffffu, mx0, 2));
        mx1 = fmaxf(mx1, __shfl_xor_sync(0xffffffffu, mx1, 1));
        mx1 = fmaxf(mx1, __shfl_xor_sync(0xffffffffu, mx1, 2));

        const float nm0 = fmaxf(m0, mx0);
        const float nm1 = fmaxf(m1, mx1);
        const float corr0 = __expf(m0 - nm0);
        const float corr1 = __expf(m1 - nm1);
        m0 = nm0; m1 = nm1;

        uint32_t ph0[8], ph1[8];
        float sum0 = 0.f, sum1 = 0.f;
#pragma unroll
        for (int nt = 0; nt < 8; nt++) {
            const float p0 = __expf(sacc[nt][0] - nm0);
            const float p1 = __expf(sacc[nt][1] - nm0);
            const float p2 = __expf(sacc[nt][2] - nm1);
            const float p3 = __expf(sacc[nt][3] - nm1);
            sum0 += p0 + p1;
            sum1 += p2 + p3;
            ph0[nt] = pack_h2(p0, p1);
            ph1[nt] = pack_h2(p2, p3);
            oacc[nt][0] *= corr0; oacc[nt][1] *= corr0;
            oacc[nt][2] *= corr1; oacc[nt][3] *= corr1;
        }
        l0 = l0 * corr0 + sum0;
        l1 = l1 * corr1 + sum1;

        // ---- O += P V ----
#pragma unroll
        for (int kc = 0; kc < 4; kc++) {
            uint32_t a[4] = {ph0[2 * kc], ph1[2 * kc],
                             ph0[2 * kc + 1], ph1[2 * kc + 1]};
#pragma unroll
            for (int ntp = 0; ntp < 4; ntp++) {
                uint32_t t4[4];
                ldm_x4t(t4, vsS + (kc * 16 + mat2 * 8 + l8) * 144
                            + (ntp * 2 + hi) * 16);
                uint32_t v0[2] = {t4[0], t4[1]};
                uint32_t v1[2] = {t4[2], t4[3]};
                mma_f16(oacc[2 * ntp], a, v0);
                mma_f16(oacc[2 * ntp + 1], a, v1);
            }
        }
        __syncthreads();   // stage reuse gate
    }

    l0 += __shfl_xor_sync(0xffffffffu, l0, 1);
    l0 += __shfl_xor_sync(0xffffffffu, l0, 2);
    l1 += __shfl_xor_sync(0xffffffffu, l1, 1);
    l1 += __shfl_xor_sync(0xffffffffu, l1, 2);
    const float inv0 = 1.0f / l0;
    const float inv1 = 1.0f / l1;

    __half* y0 = &g_Y[((size_t)(b * Td + qrow0)) * Cd + h * HSd];
    __half* y1 = &g_Y[((size_t)(b * Td + qrow1)) * Cd + h * HSd];
#pragma unroll
    for (int nt = 0; nt < 8; nt++) {
        const int c = nt * 8 + 2 * tig;
        *(__half2*)&y0[c] = __floats2half2_rn(oacc[nt][0] * inv0,
                                              oacc[nt][1] * inv0);
        *(__half2*)&y1[c] = __floats2half2_rn(oacc[nt][2] * inv1,
                                              oacc[nt][3] * inv1);
    }
}

// ---------------- host launch ------------------------------------------------
typedef CUresult (*PFN_tmEncode)(
    CUtensorMap*, CUtensorMapDataType, cuuint32_t, void*,
    const cuuint64_t*, const cuuint64_t*, const cuuint32_t*, const cuuint32_t*,
    CUtensorMapInterleave, CUtensorMapSwizzle, CUtensorMapL2promotion,
    CUtensorMapFloatOOBfill);

static bool make_map(PFN_tmEncode enc, CUtensorMap* tm, void* base, uint64_t rows)
{
    cuuint64_t dims[2]    = {(cuuint64_t)KDIM, (cuuint64_t)rows};
    cuuint64_t strides[1] = {(cuuint64_t)KDIM * 2};
    cuuint32_t box[2]     = {64, 128};
    cuuint32_t es[2]      = {1, 1};
    CUresult r = enc(tm, CU_TENSOR_MAP_DATA_TYPE_FLOAT16, 2, base, dims, strides,
                     box, es, CU_TENSOR_MAP_INTERLEAVE_NONE,
                     CU_TENSOR_MAP_SWIZZLE_128B,
                     CU_TENSOR_MAP_L2_PROMOTION_L2_128B,
                     CU_TENSOR_MAP_FLOAT_OOB_FILL_NONE);
    return r == CUDA_SUCCESS;
}

extern "C" void kernel_launch(void* const* d_in, const int* in_sizes, int n_in,
                              void* d_out, int out_size)
{
    const float* x      = (const float*)d_in[0];
    const float* W_attn = (const float*)d_in[1];
    const float* b_attn = (const float*)d_in[2];
    const float* W_proj = (const float*)d_in[3];
    const float* b_proj = (const float*)d_in[4];
    float* out = (float*)d_out;

    (void)in_sizes; (void)n_in; (void)out_size;

    void *p_xh, *p_wat, *p_wpt, *p_y;
    cudaGetSymbolAddress(&p_xh,  g_xh);
    cudaGetSymbolAddress(&p_wat, g_WAt);
    cudaGetSymbolAddress(&p_wpt, g_WPt);
    cudaGetSymbolAddress(&p_y,   g_Y);

    static CUtensorMap h_maps[4];
    bool use_tma = false;
    {
        void* fn = nullptr;
        cudaDriverEntryPointQueryResult qs =
            cudaDriverEntryPointSymbolNotFound;
        cudaError_t e = cudaGetDriverEntryPoint("cuTensorMapEncodeTiled", &fn,
                                                cudaEnableDefault, &qs);
        if (e == cudaSuccess && fn && qs == cudaDriverEntryPointSuccess) {
            PFN_tmEncode enc = (PFN_tmEncode)fn;
            bool ok = make_map(enc, &h_maps[0], p_xh,  Md)
                   && make_map(enc, &h_maps[1], p_wat, N_QKV)
                   && make_map(enc, &h_maps[2], p_wpt, Cd)
                   && make_map(enc, &h_maps[3], p_y,   Md);
            if (ok) {
                cudaMemcpyToSymbolAsync(d_tmaps, h_maps, sizeof(h_maps), 0,
                                        cudaMemcpyHostToDevice, 0);
                use_tma = true;
            }
        }
    }
    void* p_maps = nullptr;
    cudaGetSymbolAddress(&p_maps, d_tmaps);
    CUtensorMap* maps = (CUtensorMap*)p_maps;

    cudaFuncSetAttribute(gemm_sw_kernel<N_QKV, true, true>,
                         cudaFuncAttributeMaxDynamicSharedMemorySize, TC_SMEM);
    cudaFuncSetAttribute(gemm_sw_kernel<N_QKV, true, false>,
                         cudaFuncAttributeMaxDynamicSharedMemorySize, TC_SMEM);
    cudaFuncSetAttribute(gemm_sw_kernel<Cd, false, true>,
                         cudaFuncAttributeMaxDynamicSharedMemorySize, TC_SMEM);
    cudaFuncSetAttribute(gemm_sw_kernel<Cd, false, false>,
                         cudaFuncAttributeMaxDynamicSharedMemorySize, TC_SMEM);
    cudaFuncSetAttribute(attn_f16_kernel,
                         cudaFuncAttributeMaxDynamicSharedMemorySize, ATT_SMEM);

    cvt_x_kernel<<<4096, 256>>>((const float4*)x, Md * KDIM / 4);
    transpose_cvt_kernel<<<dim3(N_QKV / 32, KDIM / 32), dim3(32, 8)>>>(
        W_attn, (__half*)p_wat, KDIM, N_QKV);
    transpose_cvt_kernel<<<dim3(Cd / 32, KDIM / 32), dim3(32, 8)>>>(
        W_proj, (__half*)p_wpt, KDIM, Cd);

    dim3 gQKV(N_QKV / 128, Md / 128);     // (24, 64)
    dim3 gProj(Cd / 128, Md / 128);       // (8, 64)
    dim3 gAtt(Td / 128, NHd, Bd);         // (16, 16, 4)

    if (use_tma) {
        gemm_sw_kernel<N_QKV, true, true><<<gQKV, 256, TC_SMEM>>>(
            maps + 0, maps + 1, (const __half*)p_xh, (const __half*)p_wat,
            b_attn, nullptr);
        attn_f16_kernel<<<gAtt, 256, ATT_SMEM>>>();
        gemm_sw_kernel<Cd, false, true><<<gProj, 256, TC_SMEM>>>(
            maps + 3, maps + 2, (const __half*)p_y, (const __half*)p_wpt,
            b_proj, out);
    } else {
        gemm_sw_kernel<N_QKV, true, false><<<gQKV, 256, TC_SMEM>>>(
            nullptr, nullptr, (const __half*)p_xh, (const __half*)p_wat,
            b_attn, nullptr);
        attn_f16_kernel<<<gAtt, 256, ATT_SMEM>>>();
        gemm_sw_kernel<Cd, false, false><<<gProj, 256, TC_SMEM>>>(
            nullptr, nullptr, (const __half*)p_y, (const __half*)p_wpt,
            b_proj, out);
    }
}